// round 1
// baseline (speedup 1.0000x reference)
#include <cuda_runtime.h>

// Swin shifted-window attention, B=64, H=W=56, C=128, heads=4, hd=32, ws=7, shift=3.
// Round 1: fp32 baseline, 3 kernels staged through __device__ scratch.

#define BATCH 64
#define HW    56
#define CH    128
#define WSZ   7
#define NWS   8          // windows per side
#define NWIN  64         // windows per image
#define SEQ   49
#define HEADS 4
#define HD    32
#define DISP  3
#define SCALEF 0.5f      // HEADS^-0.5

#define XS_PITCH 68      // padded row for A^T tile (16B aligned rows, reduced bank conflicts)
#define WS_PITCH 132     // padded row for B^T tile
#define SMEM_BYTES ((128*XS_PITCH + 128*WS_PITCH) * 4)   // 102400

// scratch (allowed: __device__ globals)
__device__ float g_q[(size_t)BATCH*HEADS*NWIN*SEQ*HD];
__device__ float g_k[(size_t)BATCH*HEADS*NWIN*SEQ*HD];
__device__ float g_v[(size_t)BATCH*HEADS*NWIN*SEQ*HD];
__device__ float g_attn[(size_t)BATCH*NWIN*SEQ*CH];

// ---------------------------------------------------------------------------
// Kernel 1: fused roll + QKV projection, windowed output layout.
// One block per (batch, window). Tile: M=64 (49 real pixels), N=128, K=128.
// 256 threads, each computes a 4x8 register tile.
// ---------------------------------------------------------------------------
__global__ __launch_bounds__(256) void qkv_kernel(const float* __restrict__ x,
                                                  const float* __restrict__ w_qkv) {
    extern __shared__ float smem[];
    float* xsT = smem;                     // [k][m] 128 x 68
    float* wsT = smem + 128 * XS_PITCH;    // [k][n] 128 x 132

    const int blk = blockIdx.x;
    const int b   = blk >> 6;
    const int win = blk & 63;
    const int wr  = win >> 3, wc = win & 7;
    const int tid = threadIdx.x;

    // Load window of rolled x, transposed into smem: xsT[c][m]
    for (int idx = tid; idx < 64 * CH; idx += 256) {
        const int m = idx >> 7, c = idx & 127;
        float v = 0.f;
        if (m < SEQ) {
            const int i = m / 7, j = m - i * 7;
            int gh = wr * 7 + i + DISP; if (gh >= HW) gh -= HW;
            int gw = wc * 7 + j + DISP; if (gw >= HW) gw -= HW;
            v = x[(((size_t)b * HW + gh) * HW + gw) * CH + c];
        }
        xsT[c * XS_PITCH + m] = v;
    }

    const int tm = tid & 15, tn = tid >> 4;
    const int m0 = tm * 4, n0 = tn * 8;

    for (int chunk = 0; chunk < 3; ++chunk) {
        __syncthreads();  // xsT done (first iter) / previous wsT consumers done
        for (int idx = tid; idx < 128 * CH; idx += 256) {
            const int n = idx >> 7, k = idx & 127;
            wsT[k * WS_PITCH + n] = w_qkv[(chunk * 128 + n) * CH + k];
        }
        __syncthreads();

        float acc[4][8];
        #pragma unroll
        for (int mi = 0; mi < 4; ++mi)
            #pragma unroll
            for (int ni = 0; ni < 8; ++ni) acc[mi][ni] = 0.f;

        #pragma unroll 4
        for (int k = 0; k < 128; ++k) {
            const float4 a4 = *(const float4*)(xsT + k * XS_PITCH + m0);
            const float4 b0 = *(const float4*)(wsT + k * WS_PITCH + n0);
            const float4 b1 = *(const float4*)(wsT + k * WS_PITCH + n0 + 4);
            const float av[4] = {a4.x, a4.y, a4.z, a4.w};
            const float bv[8] = {b0.x, b0.y, b0.z, b0.w, b1.x, b1.y, b1.z, b1.w};
            #pragma unroll
            for (int mi = 0; mi < 4; ++mi)
                #pragma unroll
                for (int ni = 0; ni < 8; ++ni)
                    acc[mi][ni] += av[mi] * bv[ni];
        }

        float* gout = (chunk == 0) ? g_q : (chunk == 1) ? g_k : g_v;
        const int head = n0 >> 5, d0 = n0 & 31;
        const size_t base = (((size_t)b * HEADS + head) * NWIN + win) * SEQ;
        #pragma unroll
        for (int mi = 0; mi < 4; ++mi) {
            const int m = m0 + mi;
            if (m < SEQ) {
                float* o = gout + (base + m) * HD + d0;
                *(float4*)(o)     = make_float4(acc[mi][0], acc[mi][1], acc[mi][2], acc[mi][3]);
                *(float4*)(o + 4) = make_float4(acc[mi][4], acc[mi][5], acc[mi][6], acc[mi][7]);
            }
        }
    }
}

// ---------------------------------------------------------------------------
// Kernel 2: windowed attention. One block per (b, win, head), 64 threads.
// Thread i (<49) owns score row i. Bias + shift mask + softmax + PV fused.
// ---------------------------------------------------------------------------
__global__ __launch_bounds__(64) void attn_kernel(const float* __restrict__ pos) {
    __shared__ float qs[SEQ * HD];
    __shared__ float ks[SEQ * HD];
    __shared__ float vs[SEQ * HD];
    __shared__ float ps[169];
    __shared__ float ss[SEQ * 57];

    const int blk  = blockIdx.x;           // ((b*64 + win)*4 + head)
    const int head = blk & 3;
    const int win  = (blk >> 2) & 63;
    const int b    = blk >> 8;
    const int tid  = threadIdx.x;
    const size_t base = (((size_t)b * HEADS + head) * NWIN + win) * SEQ * HD;

    for (int idx = tid; idx < SEQ * HD; idx += 64) {
        qs[idx] = g_q[base + idx];
        ks[idx] = g_k[base + idx];
        vs[idx] = g_v[base + idx];
    }
    for (int idx = tid; idx < 169; idx += 64) ps[idx] = pos[idx];
    __syncthreads();

    const int wr = win >> 3, wc = win & 7;
    const bool mU = (wr == 7), mL = (wc == 7);

    if (tid < SEQ) {
        const int i = tid;
        const int xi = i / 7, yi = i - xi * 7;
        float qreg[HD];
        #pragma unroll
        for (int k = 0; k < HD; ++k) qreg[k] = qs[i * HD + k];

        // scores row + bias + mask
        for (int j = 0; j < SEQ; ++j) {
            const float4* kr = (const float4*)(ks + j * HD);
            float acc = 0.f;
            #pragma unroll
            for (int k = 0; k < 8; ++k) {
                const float4 kv = kr[k];
                acc += qreg[4*k]   * kv.x;
                acc += qreg[4*k+1] * kv.y;
                acc += qreg[4*k+2] * kv.z;
                acc += qreg[4*k+3] * kv.w;
            }
            const int xj = j / 7, yj = j - xj * 7;
            float sv = acc * SCALEF + ps[(xj - xi + 6) * 13 + (yj - yi + 6)];
            if ((mU && ((xi >= 4) != (xj >= 4))) || (mL && ((yi >= 4) != (yj >= 4))))
                sv = -1e30f;
            ss[i * 57 + j] = sv;
        }

        // softmax (row-private)
        float mx = -1e30f;
        for (int j = 0; j < SEQ; ++j) mx = fmaxf(mx, ss[i * 57 + j]);
        float sum = 0.f;
        for (int j = 0; j < SEQ; ++j) {
            const float e = __expf(ss[i * 57 + j] - mx);
            ss[i * 57 + j] = e;
            sum += e;
        }
        const float inv = 1.0f / sum;

        // PV
        float acc[HD];
        #pragma unroll
        for (int k = 0; k < HD; ++k) acc[k] = 0.f;
        for (int j = 0; j < SEQ; ++j) {
            const float p = ss[i * 57 + j];
            const float4* vr = (const float4*)(vs + j * HD);
            #pragma unroll
            for (int k = 0; k < 8; ++k) {
                const float4 vv = vr[k];
                acc[4*k]   += p * vv.x;
                acc[4*k+1] += p * vv.y;
                acc[4*k+2] += p * vv.z;
                acc[4*k+3] += p * vv.w;
            }
        }
        const size_t obase = (((size_t)b * NWIN + win) * SEQ + i) * CH + head * HD;
        #pragma unroll
        for (int k = 0; k < 8; ++k)
            *(float4*)(g_attn + obase + 4 * k) =
                make_float4(acc[4*k] * inv, acc[4*k+1] * inv, acc[4*k+2] * inv, acc[4*k+3] * inv);
    }
}

// ---------------------------------------------------------------------------
// Kernel 3: output projection + bias, fused un-window + inverse roll scatter.
// Same GEMM skeleton as kernel 1, single N=128 chunk.
// ---------------------------------------------------------------------------
__global__ __launch_bounds__(256) void proj_kernel(const float* __restrict__ w_out,
                                                   const float* __restrict__ b_out,
                                                   float* __restrict__ out) {
    extern __shared__ float smem[];
    float* xsT = smem;
    float* wsT = smem + 128 * XS_PITCH;

    const int blk = blockIdx.x;
    const int b   = blk >> 6;
    const int win = blk & 63;
    const int wr  = win >> 3, wc = win & 7;
    const int tid = threadIdx.x;

    for (int idx = tid; idx < 64 * CH; idx += 256) {
        const int m = idx >> 7, c = idx & 127;
        float v = 0.f;
        if (m < SEQ)
            v = g_attn[(((size_t)b * NWIN + win) * SEQ + m) * CH + c];
        xsT[c * XS_PITCH + m] = v;
    }
    for (int idx = tid; idx < 128 * CH; idx += 256) {
        const int n = idx >> 7, k = idx & 127;
        wsT[k * WS_PITCH + n] = w_out[n * CH + k];
    }
    __syncthreads();

    const int tm = tid & 15, tn = tid >> 4;
    const int m0 = tm * 4, n0 = tn * 8;

    float bias[8];
    #pragma unroll
    for (int ni = 0; ni < 8; ++ni) bias[ni] = b_out[n0 + ni];

    float acc[4][8];
    #pragma unroll
    for (int mi = 0; mi < 4; ++mi)
        #pragma unroll
        for (int ni = 0; ni < 8; ++ni) acc[mi][ni] = bias[ni];

    #pragma unroll 4
    for (int k = 0; k < 128; ++k) {
        const float4 a4 = *(const float4*)(xsT + k * XS_PITCH + m0);
        const float4 b0 = *(const float4*)(wsT + k * WS_PITCH + n0);
        const float4 b1 = *(const float4*)(wsT + k * WS_PITCH + n0 + 4);
        const float av[4] = {a4.x, a4.y, a4.z, a4.w};
        const float bv[8] = {b0.x, b0.y, b0.z, b0.w, b1.x, b1.y, b1.z, b1.w};
        #pragma unroll
        for (int mi = 0; mi < 4; ++mi)
            #pragma unroll
            for (int ni = 0; ni < 8; ++ni)
                acc[mi][ni] += av[mi] * bv[ni];
    }

    #pragma unroll
    for (int mi = 0; mi < 4; ++mi) {
        const int m = m0 + mi;
        if (m < SEQ) {
            const int i = m / 7, j = m - i * 7;
            int gh = wr * 7 + i + DISP; if (gh >= HW) gh -= HW;   // inverse roll (+3)
            int gw = wc * 7 + j + DISP; if (gw >= HW) gw -= HW;
            float* o = out + (((size_t)b * HW + gh) * HW + gw) * CH + n0;
            *(float4*)(o)     = make_float4(acc[mi][0], acc[mi][1], acc[mi][2], acc[mi][3]);
            *(float4*)(o + 4) = make_float4(acc[mi][4], acc[mi][5], acc[mi][6], acc[mi][7]);
        }
    }
}

extern "C" void kernel_launch(void* const* d_in, const int* in_sizes, int n_in,
                              void* d_out, int out_size) {
    const float* x      = (const float*)d_in[0];
    const float* w_qkv  = (const float*)d_in[1];
    const float* pos    = (const float*)d_in[2];
    const float* w_out  = (const float*)d_in[3];
    const float* b_out  = (const float*)d_in[4];
    float* out = (float*)d_out;

    cudaFuncSetAttribute(qkv_kernel,  cudaFuncAttributeMaxDynamicSharedMemorySize, SMEM_BYTES);
    cudaFuncSetAttribute(proj_kernel, cudaFuncAttributeMaxDynamicSharedMemorySize, SMEM_BYTES);

    qkv_kernel<<<BATCH * NWIN, 256, SMEM_BYTES>>>(x, w_qkv);
    attn_kernel<<<BATCH * NWIN * HEADS, 64>>>(pos);
    proj_kernel<<<BATCH * NWIN, 256, SMEM_BYTES>>>(w_out, b_out, out);
}

// round 2
// speedup vs baseline: 1.8652x; 1.8652x over previous
#include <cuda_runtime.h>
#include <cstdint>

// Swin shifted-window attention, B=64, H=W=56, C=128, heads=4, hd=32, ws=7, shift=3.
// Round 2: QKV + output-proj GEMMs on tensor cores (mma.sync tf32), attn kernel unchanged.

#define BATCH 64
#define HW    56
#define CH    128
#define NWIN  64
#define SEQ   49
#define HEADS 4
#define HD    32
#define DISP  3
#define SCALEF 0.5f
#define MPB   3136        // windowed rows per batch (64 windows * 49)
#define MTILES 25         // ceil(3136/128)
#define PK    132         // smem pitch (floats) for [*][k] tiles
#define GEMM_SMEM (2 * 128 * PK * 4)

// scratch
__device__ float g_q[(size_t)BATCH*HEADS*NWIN*SEQ*HD];
__device__ float g_k[(size_t)BATCH*HEADS*NWIN*SEQ*HD];
__device__ float g_v[(size_t)BATCH*HEADS*NWIN*SEQ*HD];
__device__ float g_attn[(size_t)BATCH*NWIN*SEQ*CH];

__device__ __forceinline__ uint32_t f2tf(float f) {
    uint32_t u; asm("cvt.rna.tf32.f32 %0, %1;" : "=r"(u) : "f"(f)); return u;
}

__device__ __forceinline__ void mma8(float* c, const uint32_t* a, const uint32_t* b) {
    asm volatile(
        "mma.sync.aligned.m16n8k8.row.col.f32.tf32.tf32.f32 "
        "{%0,%1,%2,%3}, {%4,%5,%6,%7}, {%8,%9}, {%0,%1,%2,%3};\n"
        : "+f"(c[0]), "+f"(c[1]), "+f"(c[2]), "+f"(c[3])
        : "r"(a[0]), "r"(a[1]), "r"(a[2]), "r"(a[3]), "r"(b[0]), "r"(b[1]));
}

// ---------------------------------------------------------------------------
// Kernel 1: fused roll + QKV projection on tensor cores.
// grid = (25 mtiles, 3 ntiles/chunks, 64 batches), block = 256.
// C[128m x 128n] = A[128m x 128k] * B^T, A gathered from rolled x in windowed
// M order, B = w_qkv chunk. Epilogue scatters to windowed q/k/v scratch.
// ---------------------------------------------------------------------------
__global__ __launch_bounds__(256, 1) void qkv_mma_kernel(const float* __restrict__ x,
                                                         const float* __restrict__ w_qkv) {
    extern __shared__ uint32_t sh[];
    uint32_t* As = sh;              // [m][k], pitch PK
    uint32_t* Bs = sh + 128 * PK;   // [n][k], pitch PK

    const int mtile = blockIdx.x, ntile = blockIdx.y, b = blockIdx.z;
    const int tid = threadIdx.x, lane = tid & 31, wid = tid >> 5;

    // ---- load A tile: 128 windowed-M rows of rolled x (tf32 in smem) ----
    {
        const int r = tid >> 1, half = tid & 1;
        const int m = mtile * 128 + r;
        uint32_t* dst = As + r * PK + half * 64;
        if (m < MPB) {
            const int win = m / 49, s = m - win * 49;
            const int wr = win >> 3, wc = win & 7;
            const int i = s / 7, j = s - i * 7;
            int gh = wr * 7 + i + DISP; if (gh >= HW) gh -= HW;
            int gw = wc * 7 + j + DISP; if (gw >= HW) gw -= HW;
            const float4* src = (const float4*)(x + (((size_t)b * HW + gh) * HW + gw) * CH + half * 64);
            #pragma unroll
            for (int v = 0; v < 16; ++v) {
                const float4 f = src[v];
                *(uint4*)(dst + v * 4) = make_uint4(f2tf(f.x), f2tf(f.y), f2tf(f.z), f2tf(f.w));
            }
        } else {
            #pragma unroll
            for (int v = 0; v < 16; ++v) *(uint4*)(dst + v * 4) = make_uint4(0, 0, 0, 0);
        }
    }
    // ---- load B tile: w_qkv rows [ntile*128 + n][k] ----
    {
        const int n = tid >> 1, half = tid & 1;
        const float4* src = (const float4*)(w_qkv + ((size_t)(ntile * 128 + n)) * CH + half * 64);
        uint32_t* dst = Bs + n * PK + half * 64;
        #pragma unroll
        for (int v = 0; v < 16; ++v) {
            const float4 f = src[v];
            *(uint4*)(dst + v * 4) = make_uint4(f2tf(f.x), f2tf(f.y), f2tf(f.z), f2tf(f.w));
        }
    }
    __syncthreads();

    // ---- mainloop: warp computes 32x64 via 2x8 m16n8k8 tiles ----
    const int wm = wid & 3, wn = wid >> 2;
    const int m0 = wm * 32, n0 = wn * 64;

    float acc[2][8][4];
    #pragma unroll
    for (int mt = 0; mt < 2; ++mt)
        #pragma unroll
        for (int nt = 0; nt < 8; ++nt)
            #pragma unroll
            for (int q = 0; q < 4; ++q) acc[mt][nt][q] = 0.f;

    #pragma unroll
    for (int kk = 0; kk < 16; ++kk) {
        const int k0 = kk * 8;
        uint32_t a[2][4];
        #pragma unroll
        for (int mt = 0; mt < 2; ++mt) {
            const uint32_t* p = As + (m0 + mt * 16 + (lane >> 2)) * PK + k0 + (lane & 3);
            a[mt][0] = p[0]; a[mt][1] = p[8 * PK]; a[mt][2] = p[4]; a[mt][3] = p[8 * PK + 4];
        }
        #pragma unroll
        for (int nt = 0; nt < 8; ++nt) {
            const uint32_t* p = Bs + (n0 + nt * 8 + (lane >> 2)) * PK + k0 + (lane & 3);
            uint32_t bb[2] = { p[0], p[4] };
            mma8(acc[0][nt], a[0], bb);
            mma8(acc[1][nt], a[1], bb);
        }
    }

    // ---- epilogue: scatter to windowed q/k/v scratch ----
    float* gout = (ntile == 0) ? g_q : (ntile == 1) ? g_k : g_v;
    const int mbase = mtile * 128 + m0 + (lane >> 2);
    #pragma unroll
    for (int mt = 0; mt < 2; ++mt) {
        #pragma unroll
        for (int hh = 0; hh < 2; ++hh) {
            const int m = mbase + mt * 16 + hh * 8;
            if (m < MPB) {
                const int win = m / 49, s = m - win * 49;
                #pragma unroll
                for (int nt = 0; nt < 8; ++nt) {
                    const int n = n0 + nt * 8 + 2 * (lane & 3);
                    const int head = n >> 5, d = n & 31;
                    const float2 val = (hh == 0)
                        ? make_float2(acc[mt][nt][0], acc[mt][nt][1])
                        : make_float2(acc[mt][nt][2], acc[mt][nt][3]);
                    *(float2*)(gout + ((((size_t)b * HEADS + head) * NWIN + win) * SEQ + s) * HD + d) = val;
                }
            }
        }
    }
}

// ---------------------------------------------------------------------------
// Kernel 2: windowed attention (unchanged from round 1).
// ---------------------------------------------------------------------------
__global__ __launch_bounds__(64) void attn_kernel(const float* __restrict__ pos) {
    __shared__ float qs[SEQ * HD];
    __shared__ float ks[SEQ * HD];
    __shared__ float vs[SEQ * HD];
    __shared__ float ps[169];
    __shared__ float ss[SEQ * 57];

    const int blk  = blockIdx.x;
    const int head = blk & 3;
    const int win  = (blk >> 2) & 63;
    const int b    = blk >> 8;
    const int tid  = threadIdx.x;
    const size_t base = (((size_t)b * HEADS + head) * NWIN + win) * SEQ * HD;

    for (int idx = tid; idx < SEQ * HD; idx += 64) {
        qs[idx] = g_q[base + idx];
        ks[idx] = g_k[base + idx];
        vs[idx] = g_v[base + idx];
    }
    for (int idx = tid; idx < 169; idx += 64) ps[idx] = pos[idx];
    __syncthreads();

    const int wr = win >> 3, wc = win & 7;
    const bool mU = (wr == 7), mL = (wc == 7);

    if (tid < SEQ) {
        const int i = tid;
        const int xi = i / 7, yi = i - xi * 7;
        float qreg[HD];
        #pragma unroll
        for (int k = 0; k < HD; ++k) qreg[k] = qs[i * HD + k];

        for (int j = 0; j < SEQ; ++j) {
            const float4* kr = (const float4*)(ks + j * HD);
            float acc = 0.f;
            #pragma unroll
            for (int k = 0; k < 8; ++k) {
                const float4 kv = kr[k];
                acc += qreg[4*k]   * kv.x;
                acc += qreg[4*k+1] * kv.y;
                acc += qreg[4*k+2] * kv.z;
                acc += qreg[4*k+3] * kv.w;
            }
            const int xj = j / 7, yj = j - xj * 7;
            float sv = acc * SCALEF + ps[(xj - xi + 6) * 13 + (yj - yi + 6)];
            if ((mU && ((xi >= 4) != (xj >= 4))) || (mL && ((yi >= 4) != (yj >= 4))))
                sv = -1e30f;
            ss[i * 57 + j] = sv;
        }

        float mx = -1e30f;
        for (int j = 0; j < SEQ; ++j) mx = fmaxf(mx, ss[i * 57 + j]);
        float sum = 0.f;
        for (int j = 0; j < SEQ; ++j) {
            const float e = __expf(ss[i * 57 + j] - mx);
            ss[i * 57 + j] = e;
            sum += e;
        }
        const float inv = 1.0f / sum;

        float acc[HD];
        #pragma unroll
        for (int k = 0; k < HD; ++k) acc[k] = 0.f;
        for (int j = 0; j < SEQ; ++j) {
            const float p = ss[i * 57 + j];
            const float4* vr = (const float4*)(vs + j * HD);
            #pragma unroll
            for (int k = 0; k < 8; ++k) {
                const float4 vv = vr[k];
                acc[4*k]   += p * vv.x;
                acc[4*k+1] += p * vv.y;
                acc[4*k+2] += p * vv.z;
                acc[4*k+3] += p * vv.w;
            }
        }
        const size_t obase = (((size_t)b * NWIN + win) * SEQ + i) * CH + head * HD;
        #pragma unroll
        for (int k = 0; k < 8; ++k)
            *(float4*)(g_attn + obase + 4 * k) =
                make_float4(acc[4*k] * inv, acc[4*k+1] * inv, acc[4*k+2] * inv, acc[4*k+3] * inv);
    }
}

// ---------------------------------------------------------------------------
// Kernel 3: output projection on tensor cores + bias + inverse-roll scatter.
// grid = (25 mtiles, 1, 64 batches). A = g_attn (contiguous windowed rows).
// ---------------------------------------------------------------------------
__global__ __launch_bounds__(256, 1) void proj_mma_kernel(const float* __restrict__ w_out,
                                                          const float* __restrict__ b_out,
                                                          float* __restrict__ out) {
    extern __shared__ uint32_t sh[];
    uint32_t* As = sh;
    uint32_t* Bs = sh + 128 * PK;

    const int mtile = blockIdx.x, b = blockIdx.z;
    const int tid = threadIdx.x, lane = tid & 31, wid = tid >> 5;

    // A tile: contiguous windowed rows of g_attn
    {
        const int r = tid >> 1, half = tid & 1;
        const int m = mtile * 128 + r;
        uint32_t* dst = As + r * PK + half * 64;
        if (m < MPB) {
            const float4* src = (const float4*)(g_attn + ((size_t)b * MPB + m) * CH + half * 64);
            #pragma unroll
            for (int v = 0; v < 16; ++v) {
                const float4 f = src[v];
                *(uint4*)(dst + v * 4) = make_uint4(f2tf(f.x), f2tf(f.y), f2tf(f.z), f2tf(f.w));
            }
        } else {
            #pragma unroll
            for (int v = 0; v < 16; ++v) *(uint4*)(dst + v * 4) = make_uint4(0, 0, 0, 0);
        }
    }
    // B tile: w_out [n][k]
    {
        const int n = tid >> 1, half = tid & 1;
        const float4* src = (const float4*)(w_out + (size_t)n * CH + half * 64);
        uint32_t* dst = Bs + n * PK + half * 64;
        #pragma unroll
        for (int v = 0; v < 16; ++v) {
            const float4 f = src[v];
            *(uint4*)(dst + v * 4) = make_uint4(f2tf(f.x), f2tf(f.y), f2tf(f.z), f2tf(f.w));
        }
    }
    __syncthreads();

    const int wm = wid & 3, wn = wid >> 2;
    const int m0 = wm * 32, n0 = wn * 64;

    float acc[2][8][4];
    #pragma unroll
    for (int mt = 0; mt < 2; ++mt)
        #pragma unroll
        for (int nt = 0; nt < 8; ++nt)
            #pragma unroll
            for (int q = 0; q < 4; ++q) acc[mt][nt][q] = 0.f;

    #pragma unroll
    for (int kk = 0; kk < 16; ++kk) {
        const int k0 = kk * 8;
        uint32_t a[2][4];
        #pragma unroll
        for (int mt = 0; mt < 2; ++mt) {
            const uint32_t* p = As + (m0 + mt * 16 + (lane >> 2)) * PK + k0 + (lane & 3);
            a[mt][0] = p[0]; a[mt][1] = p[8 * PK]; a[mt][2] = p[4]; a[mt][3] = p[8 * PK + 4];
        }
        #pragma unroll
        for (int nt = 0; nt < 8; ++nt) {
            const uint32_t* p = Bs + (n0 + nt * 8 + (lane >> 2)) * PK + k0 + (lane & 3);
            uint32_t bb[2] = { p[0], p[4] };
            mma8(acc[0][nt], a[0], bb);
            mma8(acc[1][nt], a[1], bb);
        }
    }

    // epilogue: bias + un-window + inverse roll
    const int mbase = mtile * 128 + m0 + (lane >> 2);
    #pragma unroll
    for (int mt = 0; mt < 2; ++mt) {
        #pragma unroll
        for (int hh = 0; hh < 2; ++hh) {
            const int m = mbase + mt * 16 + hh * 8;
            if (m < MPB) {
                const int win = m / 49, s = m - win * 49;
                const int wr = win >> 3, wc = win & 7;
                const int i = s / 7, j = s - i * 7;
                int gh = wr * 7 + i + DISP; if (gh >= HW) gh -= HW;
                int gw = wc * 7 + j + DISP; if (gw >= HW) gw -= HW;
                float* orow = out + (((size_t)b * HW + gh) * HW + gw) * CH;
                #pragma unroll
                for (int nt = 0; nt < 8; ++nt) {
                    const int n = n0 + nt * 8 + 2 * (lane & 3);
                    float2 val = (hh == 0)
                        ? make_float2(acc[mt][nt][0], acc[mt][nt][1])
                        : make_float2(acc[mt][nt][2], acc[mt][nt][3]);
                    val.x += __ldg(b_out + n);
                    val.y += __ldg(b_out + n + 1);
                    *(float2*)(orow + n) = val;
                }
            }
        }
    }
}

extern "C" void kernel_launch(void* const* d_in, const int* in_sizes, int n_in,
                              void* d_out, int out_size) {
    const float* x      = (const float*)d_in[0];
    const float* w_qkv  = (const float*)d_in[1];
    const float* pos    = (const float*)d_in[2];
    const float* w_out  = (const float*)d_in[3];
    const float* b_out  = (const float*)d_in[4];
    float* out = (float*)d_out;

    cudaFuncSetAttribute(qkv_mma_kernel,  cudaFuncAttributeMaxDynamicSharedMemorySize, GEMM_SMEM);
    cudaFuncSetAttribute(proj_mma_kernel, cudaFuncAttributeMaxDynamicSharedMemorySize, GEMM_SMEM);

    qkv_mma_kernel<<<dim3(MTILES, 3, BATCH), 256, GEMM_SMEM>>>(x, w_qkv);
    attn_kernel<<<BATCH * NWIN * HEADS, 64>>>(pos);
    proj_mma_kernel<<<dim3(MTILES, 1, BATCH), 256, GEMM_SMEM>>>(w_out, b_out, out);
}

// round 5
// speedup vs baseline: 2.2051x; 1.1822x over previous
#include <cuda_runtime.h>
#include <cstdint>

// Swin shifted-window attention, B=64, H=W=56, C=128, heads=4, hd=32, ws=7, shift=3.
// Round 3: all three stages on tensor cores (mma.sync tf32).
//  - GEMMs: M=64 block tiles (2 CTA/SM), pair-interleaved smem => LDS.64 frags.
//  - attn: per (b,win,head) mma attention with in-register softmax.

#define BATCH 64
#define HW    56
#define CH    128
#define NWIN  64
#define SEQ   49
#define HEADS 4
#define HD    32
#define DISP  3
#define MPB   3136        // windowed rows per batch (64*49)
#define MT64  49          // 3136/64
#define PK    132         // gemm smem pitch (u32)
#define GEMM_SMEM ((64 + 128) * PK * 4)   // 101376 B -> 2 CTA/SM

__device__ float g_q[(size_t)BATCH*HEADS*NWIN*SEQ*HD];
__device__ float g_k[(size_t)BATCH*HEADS*NWIN*SEQ*HD];
__device__ float g_v[(size_t)BATCH*HEADS*NWIN*SEQ*HD];
__device__ float g_attn[(size_t)BATCH*NWIN*SEQ*CH];

__device__ __forceinline__ uint32_t f2tf(float f) {
    uint32_t u; asm("cvt.rna.tf32.f32 %0, %1;" : "=r"(u) : "f"(f)); return u;
}

__device__ __forceinline__ void mma8(float* c, const uint32_t* a, uint2 b) {
    asm volatile(
        "mma.sync.aligned.m16n8k8.row.col.f32.tf32.tf32.f32 "
        "{%0,%1,%2,%3}, {%4,%5,%6,%7}, {%8,%9}, {%0,%1,%2,%3};\n"
        : "+f"(c[0]), "+f"(c[1]), "+f"(c[2]), "+f"(c[3])
        : "r"(a[0]), "r"(a[1]), "r"(a[2]), "r"(a[3]), "r"(b.x), "r"(b.y));
}

// store one 8-float group (f0 = cols g..g+3, f1 = cols g+4..g+7) pair-interleaved:
// (k, k+4) adjacent -> fragment loads become LDS.64.
__device__ __forceinline__ void st_pairs(uint32_t* dst, float4 f0, float4 f1) {
    *(uint2*)(dst + 0) = make_uint2(f2tf(f0.x), f2tf(f1.x));
    *(uint2*)(dst + 2) = make_uint2(f2tf(f0.y), f2tf(f1.y));
    *(uint2*)(dst + 4) = make_uint2(f2tf(f0.z), f2tf(f1.z));
    *(uint2*)(dst + 6) = make_uint2(f2tf(f0.w), f2tf(f1.w));
}
// permuted column index for scalar stores into pair-interleaved layout
__device__ __forceinline__ int pcol(int c) {
    return (c & ~7) + ((c & 3) << 1) + ((c >> 2) & 1);
}

// ---------------------------------------------------------------------------
// Kernel 1: fused roll + QKV projection. grid (49, 3 chunks, 64 batches).
// block 256 = 8 warps (2m x 4n), warp tile 32x32. C = A[64x128] * B[128x128]^T.
// ---------------------------------------------------------------------------
__global__ __launch_bounds__(256, 2) void qkv_mma_kernel(const float* __restrict__ x,
                                                         const float* __restrict__ w_qkv) {
    extern __shared__ uint32_t sh[];
    uint32_t* As = sh;             // [64][PK]
    uint32_t* Bs = sh + 64 * PK;   // [128][PK]

    const int mtile = blockIdx.x, ntile = blockIdx.y, b = blockIdx.z;
    const int tid = threadIdx.x, lane = tid & 31, wid = tid >> 5;

    // A: 64 rows x 128 cols, rolled-window gather. 1024 8-float units.
    #pragma unroll
    for (int it = 0; it < 4; ++it) {
        const int idx = tid + 256 * it;
        const int row = idx >> 4, gb = (idx & 15) * 8;
        const int m = mtile * 64 + row;
        const int win = m / 49, s = m - win * 49;
        const int wr = win >> 3, wc = win & 7;
        const int i = s / 7, j = s - i * 7;
        int gh = wr * 7 + i + DISP; if (gh >= HW) gh -= HW;
        int gw = wc * 7 + j + DISP; if (gw >= HW) gw -= HW;
        const float4* sp = (const float4*)(x + (((size_t)b * HW + gh) * HW + gw) * CH + gb);
        st_pairs(As + row * PK + gb, sp[0], sp[1]);
    }
    // B: w_qkv chunk, 128x128. 2048 units.
    #pragma unroll
    for (int it = 0; it < 8; ++it) {
        const int idx = tid + 256 * it;
        const int row = idx >> 4, gb = (idx & 15) * 8;
        const float4* sp = (const float4*)(w_qkv + ((size_t)(ntile * 128 + row)) * CH + gb);
        st_pairs(Bs + row * PK + gb, sp[0], sp[1]);
    }
    __syncthreads();

    const int wm = wid & 1, wn = wid >> 1;
    const int m0 = wm * 32, n0 = wn * 32;

    float acc[2][4][4];
    #pragma unroll
    for (int mt = 0; mt < 2; ++mt)
        #pragma unroll
        for (int nt = 0; nt < 4; ++nt)
            #pragma unroll
            for (int q = 0; q < 4; ++q) acc[mt][nt][q] = 0.f;

    #pragma unroll
    for (int kk = 0; kk < 16; ++kk) {
        const int k0 = kk * 8 + 2 * (lane & 3);
        const uint32_t* ar = As + (m0 + (lane >> 2)) * PK + k0;
        const uint2 A10 = *(const uint2*)(ar);
        const uint2 A11 = *(const uint2*)(ar + 8 * PK);
        const uint2 A20 = *(const uint2*)(ar + 16 * PK);
        const uint2 A21 = *(const uint2*)(ar + 24 * PK);
        const uint32_t a0[4] = {A10.x, A11.x, A10.y, A11.y};
        const uint32_t a1[4] = {A20.x, A21.x, A20.y, A21.y};
        #pragma unroll
        for (int nt = 0; nt < 4; ++nt) {
            const uint2 B = *(const uint2*)(Bs + (n0 + nt * 8 + (lane >> 2)) * PK + k0);
            mma8(acc[0][nt], a0, B);
            mma8(acc[1][nt], a1, B);
        }
    }

    float* gout = (ntile == 0) ? g_q : (ntile == 1) ? g_k : g_v;
    #pragma unroll
    for (int mt = 0; mt < 2; ++mt) {
        #pragma unroll
        for (int hh = 0; hh < 2; ++hh) {
            const int m = mtile * 64 + m0 + mt * 16 + hh * 8 + (lane >> 2);
            const int win = m / 49, s = m - win * 49;
            const int head = wn;
            #pragma unroll
            for (int nt = 0; nt < 4; ++nt) {
                const int d = nt * 8 + 2 * (lane & 3);
                const float2 val = (hh == 0)
                    ? make_float2(acc[mt][nt][0], acc[mt][nt][1])
                    : make_float2(acc[mt][nt][2], acc[mt][nt][3]);
                *(float2*)(gout + ((((size_t)b * HEADS + head) * NWIN + win) * SEQ + s) * HD + d) = val;
            }
        }
    }
}

// ---------------------------------------------------------------------------
// Kernel 2: mma attention. One block per (b, win, head), 128 threads = 4 warps.
// Warp w owns score rows 16w..16w+15 (padded 64x64, real 49x49).
// ---------------------------------------------------------------------------
__global__ __launch_bounds__(128, 4) void attn_mma_kernel(const float* __restrict__ pos) {
    __shared__ uint32_t Kt[64 * 36];   // [n][k] tf32, pair-interleaved k
    __shared__ uint32_t VT[32 * 68];   // [d][j] tf32, pair-interleaved j
    __shared__ uint32_t Ps[64 * 68];   // [i][j] probs tf32, pair-interleaved j
    __shared__ float    ps[172];

    const int blk  = blockIdx.x;
    const int head = blk & 3;
    const int win  = (blk >> 2) & 63;
    const int b    = blk >> 8;
    const int tid  = threadIdx.x, lane = tid & 31, w = tid >> 5;
    const size_t base = (((size_t)b * HEADS + head) * NWIN + win) * SEQ * HD;

    // K -> Kt[64][36] (rows >=49 zero)
    {
        const int r = tid >> 1, h = tid & 1;
        uint32_t* dst = Kt + r * 36 + h * 16;
        if (r < SEQ) {
            const float4* sp = (const float4*)(g_k + base + r * HD + h * 16);
            st_pairs(dst,     sp[0], sp[1]);
            st_pairs(dst + 8, sp[2], sp[3]);
        } else {
            #pragma unroll
            for (int v = 0; v < 16; ++v) dst[v] = 0;
        }
    }
    // V -> VT[32][68] transposed (cols j>=49 zero)
    for (int idx = tid; idx < 32 * 64; idx += 128) {
        const int j = idx >> 5, d = idx & 31;
        const float v = (j < SEQ) ? g_v[base + j * HD + d] : 0.f;
        VT[d * 68 + pcol(j)] = f2tf(v);
    }
    for (int idx = tid; idx < 169; idx += 128) ps[idx] = pos[idx];
    __syncthreads();

    // Q fragments straight from gmem (scale folded in)
    const int r1 = 16 * w + (lane >> 2), r2 = r1 + 8;
    uint32_t a[4][4];
    {
        const float* qb = g_q + base;
        #pragma unroll
        for (int kk = 0; kk < 4; ++kk) {
            const int k = kk * 8 + (lane & 3);
            a[kk][0] = (r1 < SEQ) ? f2tf(0.5f * __ldg(qb + r1 * HD + k))     : 0u;
            a[kk][1] = (r2 < SEQ) ? f2tf(0.5f * __ldg(qb + r2 * HD + k))     : 0u;
            a[kk][2] = (r1 < SEQ) ? f2tf(0.5f * __ldg(qb + r1 * HD + k + 4)) : 0u;
            a[kk][3] = (r2 < SEQ) ? f2tf(0.5f * __ldg(qb + r2 * HD + k + 4)) : 0u;
        }
    }

    // scores: 16x64 per warp
    float c[8][4];
    #pragma unroll
    for (int nt = 0; nt < 8; ++nt)
        #pragma unroll
        for (int q = 0; q < 4; ++q) c[nt][q] = 0.f;
    #pragma unroll
    for (int kk = 0; kk < 4; ++kk) {
        const int k0 = kk * 8 + 2 * (lane & 3);
        #pragma unroll
        for (int nt = 0; nt < 8; ++nt) {
            const uint2 B = *(const uint2*)(Kt + (nt * 8 + (lane >> 2)) * 36 + k0);
            mma8(c[nt], a[kk], B);
        }
    }

    // bias + shift mask
    const int wr = win >> 3, wc = win & 7;
    const bool mU = (wr == 7), mL = (wc == 7);
    const int ic1 = (r1 < SEQ) ? r1 : 48, ic2 = (r2 < SEQ) ? r2 : 48;
    const int xi1 = ic1 / 7, yi1 = ic1 - 7 * xi1;
    const int xi2 = ic2 / 7, yi2 = ic2 - 7 * xi2;
    #pragma unroll
    for (int nt = 0; nt < 8; ++nt) {
        #pragma unroll
        for (int e = 0; e < 2; ++e) {
            const int jj = nt * 8 + 2 * (lane & 3) + e;
            if (jj < SEQ) {
                const int xj = jj / 7, yj = jj - 7 * xj;
                c[nt][e]     += ps[(xj - xi1 + 6) * 13 + (yj - yi1 + 6)];
                c[nt][2 + e] += ps[(xj - xi2 + 6) * 13 + (yj - yi2 + 6)];
                if ((mU && ((xi1 >= 4) != (xj >= 4))) || (mL && ((yi1 >= 4) != (yj >= 4))))
                    c[nt][e] = -1e30f;
                if ((mU && ((xi2 >= 4) != (xj >= 4))) || (mL && ((yi2 >= 4) != (yj >= 4))))
                    c[nt][2 + e] = -1e30f;
            } else {
                c[nt][e] = -1e30f;
                c[nt][2 + e] = -1e30f;
            }
        }
    }

    // softmax across the 4-lane row group (lanes sharing lane>>2)
    float mx1 = -1e30f, mx2 = -1e30f;
    #pragma unroll
    for (int nt = 0; nt < 8; ++nt) {
        mx1 = fmaxf(mx1, fmaxf(c[nt][0], c[nt][1]));
        mx2 = fmaxf(mx2, fmaxf(c[nt][2], c[nt][3]));
    }
    mx1 = fmaxf(mx1, __shfl_xor_sync(0xffffffffu, mx1, 1));
    mx1 = fmaxf(mx1, __shfl_xor_sync(0xffffffffu, mx1, 2));
    mx2 = fmaxf(mx2, __shfl_xor_sync(0xffffffffu, mx2, 1));
    mx2 = fmaxf(mx2, __shfl_xor_sync(0xffffffffu, mx2, 2));

    float sum1 = 0.f, sum2 = 0.f;
    #pragma unroll
    for (int nt = 0; nt < 8; ++nt) {
        c[nt][0] = __expf(c[nt][0] - mx1);
        c[nt][1] = __expf(c[nt][1] - mx1);
        c[nt][2] = __expf(c[nt][2] - mx2);
        c[nt][3] = __expf(c[nt][3] - mx2);
        sum1 += c[nt][0] + c[nt][1];
        sum2 += c[nt][2] + c[nt][3];
    }
    sum1 += __shfl_xor_sync(0xffffffffu, sum1, 1);
    sum1 += __shfl_xor_sync(0xffffffffu, sum1, 2);
    sum2 += __shfl_xor_sync(0xffffffffu, sum2, 1);
    sum2 += __shfl_xor_sync(0xffffffffu, sum2, 2);

    // P (unnormalized) -> smem, pair-interleaved j
    #pragma unroll
    for (int nt = 0; nt < 8; ++nt) {
        const int jc = nt * 8 + 2 * (lane & 3);
        Ps[r1 * 68 + pcol(jc)]     = f2tf(c[nt][0]);
        Ps[r1 * 68 + pcol(jc + 1)] = f2tf(c[nt][1]);
        Ps[r2 * 68 + pcol(jc)]     = f2tf(c[nt][2]);
        Ps[r2 * 68 + pcol(jc + 1)] = f2tf(c[nt][3]);
    }
    __syncwarp();

    // PV: 16x32 per warp, k = 64
    float o[4][4];
    #pragma unroll
    for (int nt = 0; nt < 4; ++nt)
        #pragma unroll
        for (int q = 0; q < 4; ++q) o[nt][q] = 0.f;
    #pragma unroll
    for (int kk = 0; kk < 8; ++kk) {
        const int k0 = kk * 8 + 2 * (lane & 3);
        const uint2 P1 = *(const uint2*)(Ps + r1 * 68 + k0);
        const uint2 P2 = *(const uint2*)(Ps + r2 * 68 + k0);
        const uint32_t ap[4] = {P1.x, P2.x, P1.y, P2.y};
        #pragma unroll
        for (int nt = 0; nt < 4; ++nt) {
            const uint2 B = *(const uint2*)(VT + (nt * 8 + (lane >> 2)) * 68 + k0);
            mma8(o[nt], ap, B);
        }
    }

    const float inv1 = 1.f / sum1, inv2 = 1.f / sum2;
    #pragma unroll
    for (int nt = 0; nt < 4; ++nt) {
        const int d = nt * 8 + 2 * (lane & 3);
        if (r1 < SEQ)
            *(float2*)(g_attn + (((size_t)b * NWIN + win) * SEQ + r1) * CH + head * HD + d) =
                make_float2(o[nt][0] * inv1, o[nt][1] * inv1);
        if (r2 < SEQ)
            *(float2*)(g_attn + (((size_t)b * NWIN + win) * SEQ + r2) * CH + head * HD + d) =
                make_float2(o[nt][2] * inv2, o[nt][3] * inv2);
    }
}

// ---------------------------------------------------------------------------
// Kernel 3: output projection + bias + inverse-roll scatter. grid (49,1,64).
// ---------------------------------------------------------------------------
__global__ __launch_bounds__(256, 2) void proj_mma_kernel(const float* __restrict__ w_out,
                                                          const float* __restrict__ b_out,
                                                          float* __restrict__ out) {
    extern __shared__ uint32_t sh[];
    uint32_t* As = sh;
    uint32_t* Bs = sh + 64 * PK;

    const int mtile = blockIdx.x, b = blockIdx.z;
    const int tid = threadIdx.x, lane = tid & 31, wid = tid >> 5;

    #pragma unroll
    for (int it = 0; it < 4; ++it) {
        const int idx = tid + 256 * it;
        const int row = idx >> 4, gb = (idx & 15) * 8;
        const float4* sp = (const float4*)(g_attn + ((size_t)b * MPB + mtile * 64 + row) * CH + gb);
        st_pairs(As + row * PK + gb, sp[0], sp[1]);
    }
    #pragma unroll
    for (int it = 0; it < 8; ++it) {
        const int idx = tid + 256 * it;
        const int row = idx >> 4, gb = (idx & 15) * 8;
        const float4* sp = (const float4*)(w_out + (size_t)row * CH + gb);
        st_pairs(Bs + row * PK + gb, sp[0], sp[1]);
    }
    __syncthreads();

    const int wm = wid & 1, wn = wid >> 1;
    const int m0 = wm * 32, n0 = wn * 32;

    float acc[2][4][4];
    #pragma unroll
    for (int mt = 0; mt < 2; ++mt)
        #pragma unroll
        for (int nt = 0; nt < 4; ++nt)
            #pragma unroll
            for (int q = 0; q < 4; ++q) acc[mt][nt][q] = 0.f;

    #pragma unroll
    for (int kk = 0; kk < 16; ++kk) {
        const int k0 = kk * 8 + 2 * (lane & 3);
        const uint32_t* ar = As + (m0 + (lane >> 2)) * PK + k0;
        const uint2 A10 = *(const uint2*)(ar);
        const uint2 A11 = *(const uint2*)(ar + 8 * PK);
        const uint2 A20 = *(const uint2*)(ar + 16 * PK);
        const uint2 A21 = *(const uint2*)(ar + 24 * PK);
        const uint32_t a0[4] = {A10.x, A11.x, A10.y, A11.y};
        const uint32_t a1[4] = {A20.x, A21.x, A20.y, A21.y};
        #pragma unroll
        for (int nt = 0; nt < 4; ++nt) {
            const uint2 B = *(const uint2*)(Bs + (n0 + nt * 8 + (lane >> 2)) * PK + k0);
            mma8(acc[0][nt], a0, B);
            mma8(acc[1][nt], a1, B);
        }
    }

    #pragma unroll
    for (int mt = 0; mt < 2; ++mt) {
        #pragma unroll
        for (int hh = 0; hh < 2; ++hh) {
            const int m = mtile * 64 + m0 + mt * 16 + hh * 8 + (lane >> 2);
            const int win = m / 49, s = m - win * 49;
            const int wr = win >> 3, wc = win & 7;
            const int i = s / 7, j = s - i * 7;
            int gh = wr * 7 + i + DISP; if (gh >= HW) gh -= HW;
            int gw = wc * 7 + j + DISP; if (gw >= HW) gw -= HW;
            float* orow = out + (((size_t)b * HW + gh) * HW + gw) * CH;
            #pragma unroll
            for (int nt = 0; nt < 4; ++nt) {
                const int n = n0 + nt * 8 + 2 * (lane & 3);
                float2 val = (hh == 0)
                    ? make_float2(acc[mt][nt][0], acc[mt][nt][1])
                    : make_float2(acc[mt][nt][2], acc[mt][nt][3]);
                val.x += __ldg(b_out + n);
                val.y += __ldg(b_out + n + 1);
                *(float2*)(orow + n) = val;
            }
        }
    }
}

extern "C" void kernel_launch(void* const* d_in, const int* in_sizes, int n_in,
                              void* d_out, int out_size) {
    const float* x      = (const float*)d_in[0];
    const float* w_qkv  = (const float*)d_in[1];
    const float* pos    = (const float*)d_in[2];
    const float* w_out  = (const float*)d_in[3];
    const float* b_out  = (const float*)d_in[4];
    float* out = (float*)d_out;

    cudaFuncSetAttribute(qkv_mma_kernel,  cudaFuncAttributeMaxDynamicSharedMemorySize, GEMM_SMEM);
    cudaFuncSetAttribute(proj_mma_kernel, cudaFuncAttributeMaxDynamicSharedMemorySize, GEMM_SMEM);

    qkv_mma_kernel<<<dim3(MT64, 3, BATCH), 256, GEMM_SMEM>>>(x, w_qkv);
    attn_mma_kernel<<<BATCH * NWIN * HEADS, 128>>>(pos);
    proj_mma_kernel<<<dim3(MT64, 1, BATCH), 256, GEMM_SMEM>>>(w_out, b_out, out);
}

// round 8
// speedup vs baseline: 2.4254x; 1.0999x over previous
#include <cuda_runtime.h>
#include <cstdint>

// Swin shifted-window attention, B=64, H=W=56, C=128, heads=4, hd=32, ws=7, shift=3.
// Round 7: mma.sync tf32 everywhere (tcgen05 unavailable: harness targets sm_103).
// Fix vs R5: all smem pitches ≡ 8 (mod 32) -> conflict-free fragment LDS.64.

#define BATCH 64
#define HW    56
#define CH    128
#define NWIN  64
#define SEQ   49
#define HEADS 4
#define HD    32
#define DISP  3
#define MPB   3136        // windowed rows per batch (64*49)
#define MT64  49          // 3136/64
#define PK    136         // gemm smem pitch (u32), 136 mod 32 = 8 -> conflict-free
#define GEMM_SMEM ((64 + 128) * PK * 4)   // 104448 B -> 2 CTA/SM

#define KT_P  40          // attn K-tile pitch
#define PJ_P  72          // attn V/P pitch

__device__ float g_q[(size_t)BATCH*HEADS*NWIN*SEQ*HD];
__device__ float g_k[(size_t)BATCH*HEADS*NWIN*SEQ*HD];
__device__ float g_v[(size_t)BATCH*HEADS*NWIN*SEQ*HD];
__device__ float g_attn[(size_t)BATCH*NWIN*SEQ*CH];

__device__ __forceinline__ uint32_t f2tf(float f) {
    uint32_t u; asm("cvt.rna.tf32.f32 %0, %1;" : "=r"(u) : "f"(f)); return u;
}

__device__ __forceinline__ void mma8(float* c, const uint32_t* a, uint2 b) {
    asm volatile(
        "mma.sync.aligned.m16n8k8.row.col.f32.tf32.tf32.f32 "
        "{%0,%1,%2,%3}, {%4,%5,%6,%7}, {%8,%9}, {%0,%1,%2,%3};\n"
        : "+f"(c[0]), "+f"(c[1]), "+f"(c[2]), "+f"(c[3])
        : "r"(a[0]), "r"(a[1]), "r"(a[2]), "r"(a[3]), "r"(b.x), "r"(b.y));
}

// store one 8-float group (f0 = cols g..g+3, f1 = cols g+4..g+7) pair-interleaved:
// (k, k+4) adjacent -> fragment loads become LDS.64.
__device__ __forceinline__ void st_pairs(uint32_t* dst, float4 f0, float4 f1) {
    *(uint2*)(dst + 0) = make_uint2(f2tf(f0.x), f2tf(f1.x));
    *(uint2*)(dst + 2) = make_uint2(f2tf(f0.y), f2tf(f1.y));
    *(uint2*)(dst + 4) = make_uint2(f2tf(f0.z), f2tf(f1.z));
    *(uint2*)(dst + 6) = make_uint2(f2tf(f0.w), f2tf(f1.w));
}
// permuted column index for scalar stores into pair-interleaved layout
__device__ __forceinline__ int pcol(int c) {
    return (c & ~7) + ((c & 3) << 1) + ((c >> 2) & 1);
}

// ---------------------------------------------------------------------------
// Kernel 1: fused roll + QKV projection. grid (49, 3 chunks, 64 batches).
// block 256 = 8 warps (2m x 4n), warp tile 32x32. C = A[64x128] * B[128x128]^T.
// ---------------------------------------------------------------------------
__global__ __launch_bounds__(256, 2) void qkv_mma_kernel(const float* __restrict__ x,
                                                         const float* __restrict__ w_qkv) {
    extern __shared__ uint32_t sh[];
    uint32_t* As = sh;             // [64][PK]
    uint32_t* Bs = sh + 64 * PK;   // [128][PK]

    const int mtile = blockIdx.x, ntile = blockIdx.y, b = blockIdx.z;
    const int tid = threadIdx.x, lane = tid & 31, wid = tid >> 5;

    // A: 64 rows x 128 cols, rolled-window gather.
    #pragma unroll
    for (int it = 0; it < 4; ++it) {
        const int idx = tid + 256 * it;
        const int row = idx >> 4, gb = (idx & 15) * 8;
        const int m = mtile * 64 + row;
        const int win = m / 49, s = m - win * 49;
        const int wr = win >> 3, wc = win & 7;
        const int i = s / 7, j = s - i * 7;
        int gh = wr * 7 + i + DISP; if (gh >= HW) gh -= HW;
        int gw = wc * 7 + j + DISP; if (gw >= HW) gw -= HW;
        const float4* sp = (const float4*)(x + (((size_t)b * HW + gh) * HW + gw) * CH + gb);
        st_pairs(As + row * PK + gb, sp[0], sp[1]);
    }
    // B: w_qkv chunk, 128x128.
    #pragma unroll
    for (int it = 0; it < 8; ++it) {
        const int idx = tid + 256 * it;
        const int row = idx >> 4, gb = (idx & 15) * 8;
        const float4* sp = (const float4*)(w_qkv + ((size_t)(ntile * 128 + row)) * CH + gb);
        st_pairs(Bs + row * PK + gb, sp[0], sp[1]);
    }
    __syncthreads();

    const int wm = wid & 1, wn = wid >> 1;
    const int m0 = wm * 32, n0 = wn * 32;

    float acc[2][4][4];
    #pragma unroll
    for (int mt = 0; mt < 2; ++mt)
        #pragma unroll
        for (int nt = 0; nt < 4; ++nt)
            #pragma unroll
            for (int q = 0; q < 4; ++q) acc[mt][nt][q] = 0.f;

    #pragma unroll
    for (int kk = 0; kk < 16; ++kk) {
        const int k0 = kk * 8 + 2 * (lane & 3);
        const uint32_t* ar = As + (m0 + (lane >> 2)) * PK + k0;
        const uint2 A10 = *(const uint2*)(ar);
        const uint2 A11 = *(const uint2*)(ar + 8 * PK);
        const uint2 A20 = *(const uint2*)(ar + 16 * PK);
        const uint2 A21 = *(const uint2*)(ar + 24 * PK);
        const uint32_t a0[4] = {A10.x, A11.x, A10.y, A11.y};
        const uint32_t a1[4] = {A20.x, A21.x, A20.y, A21.y};
        #pragma unroll
        for (int nt = 0; nt < 4; ++nt) {
            const uint2 B = *(const uint2*)(Bs + (n0 + nt * 8 + (lane >> 2)) * PK + k0);
            mma8(acc[0][nt], a0, B);
            mma8(acc[1][nt], a1, B);
        }
    }

    float* gout = (ntile == 0) ? g_q : (ntile == 1) ? g_k : g_v;
    #pragma unroll
    for (int mt = 0; mt < 2; ++mt) {
        #pragma unroll
        for (int hh = 0; hh < 2; ++hh) {
            const int m = mtile * 64 + m0 + mt * 16 + hh * 8 + (lane >> 2);
            const int win = m / 49, s = m - win * 49;
            const int head = wn;
            #pragma unroll
            for (int nt = 0; nt < 4; ++nt) {
                const int d = nt * 8 + 2 * (lane & 3);
                const float2 val = (hh == 0)
                    ? make_float2(acc[mt][nt][0], acc[mt][nt][1])
                    : make_float2(acc[mt][nt][2], acc[mt][nt][3]);
                *(float2*)(gout + ((((size_t)b * HEADS + head) * NWIN + win) * SEQ + s) * HD + d) = val;
            }
        }
    }
}

// ---------------------------------------------------------------------------
// Kernel 2: mma attention. One block per (b, win, head), 128 threads = 4 warps.
// Warp w owns score rows 16w..16w+15 (padded 64x64, real 49x49).
// ---------------------------------------------------------------------------
__global__ __launch_bounds__(128, 4) void attn_mma_kernel(const float* __restrict__ pos) {
    __shared__ uint32_t Kt[64 * KT_P];   // [n][k] tf32, pair-interleaved k
    __shared__ uint32_t VT[32 * PJ_P];   // [d][j] tf32, pair-interleaved j
    __shared__ uint32_t Ps[64 * PJ_P];   // [i][j] probs tf32, pair-interleaved j
    __shared__ float    ps[172];

    const int blk  = blockIdx.x;
    const int head = blk & 3;
    const int win  = (blk >> 2) & 63;
    const int b    = blk >> 8;
    const int tid  = threadIdx.x, lane = tid & 31, w = tid >> 5;
    const size_t base = (((size_t)b * HEADS + head) * NWIN + win) * SEQ * HD;

    // K -> Kt (rows >=49 zero)
    {
        const int r = tid >> 1, h = tid & 1;
        uint32_t* dst = Kt + r * KT_P + h * 16;
        if (r < SEQ) {
            const float4* sp = (const float4*)(g_k + base + r * HD + h * 16);
            st_pairs(dst,     sp[0], sp[1]);
            st_pairs(dst + 8, sp[2], sp[3]);
        } else {
            #pragma unroll
            for (int v = 0; v < 16; ++v) dst[v] = 0;
        }
    }
    // V -> VT transposed (cols j>=49 zero)
    for (int idx = tid; idx < 32 * 64; idx += 128) {
        const int j = idx >> 5, d = idx & 31;
        const float v = (j < SEQ) ? g_v[base + j * HD + d] : 0.f;
        VT[d * PJ_P + pcol(j)] = f2tf(v);
    }
    for (int idx = tid; idx < 169; idx += 128) ps[idx] = pos[idx];
    __syncthreads();

    // Q fragments straight from gmem (scale folded in)
    const int r1 = 16 * w + (lane >> 2), r2 = r1 + 8;
    uint32_t a[4][4];
    {
        const float* qb = g_q + base;
        #pragma unroll
        for (int kk = 0; kk < 4; ++kk) {
            const int k = kk * 8 + (lane & 3);
            a[kk][0] = (r1 < SEQ) ? f2tf(0.5f * __ldg(qb + r1 * HD + k))     : 0u;
            a[kk][1] = (r2 < SEQ) ? f2tf(0.5f * __ldg(qb + r2 * HD + k))     : 0u;
            a[kk][2] = (r1 < SEQ) ? f2tf(0.5f * __ldg(qb + r1 * HD + k + 4)) : 0u;
            a[kk][3] = (r2 < SEQ) ? f2tf(0.5f * __ldg(qb + r2 * HD + k + 4)) : 0u;
        }
    }

    // scores: 16x64 per warp
    float c[8][4];
    #pragma unroll
    for (int nt = 0; nt < 8; ++nt)
        #pragma unroll
        for (int q = 0; q < 4; ++q) c[nt][q] = 0.f;
    #pragma unroll
    for (int kk = 0; kk < 4; ++kk) {
        const int k0 = kk * 8 + 2 * (lane & 3);
        #pragma unroll
        for (int nt = 0; nt < 8; ++nt) {
            const uint2 B = *(const uint2*)(Kt + (nt * 8 + (lane >> 2)) * KT_P + k0);
            mma8(c[nt], a[kk], B);
        }
    }

    // bias + shift mask
    const int wr = win >> 3, wc = win & 7;
    const bool mU = (wr == 7), mL = (wc == 7);
    const int ic1 = (r1 < SEQ) ? r1 : 48, ic2 = (r2 < SEQ) ? r2 : 48;
    const int xi1 = ic1 / 7, yi1 = ic1 - 7 * xi1;
    const int xi2 = ic2 / 7, yi2 = ic2 - 7 * xi2;
    #pragma unroll
    for (int nt = 0; nt < 8; ++nt) {
        #pragma unroll
        for (int e = 0; e < 2; ++e) {
            const int jj = nt * 8 + 2 * (lane & 3) + e;
            if (jj < SEQ) {
                const int xj = jj / 7, yj = jj - 7 * xj;
                c[nt][e]     += ps[(xj - xi1 + 6) * 13 + (yj - yi1 + 6)];
                c[nt][2 + e] += ps[(xj - xi2 + 6) * 13 + (yj - yi2 + 6)];
                if ((mU && ((xi1 >= 4) != (xj >= 4))) || (mL && ((yi1 >= 4) != (yj >= 4))))
                    c[nt][e] = -1e30f;
                if ((mU && ((xi2 >= 4) != (xj >= 4))) || (mL && ((yi2 >= 4) != (yj >= 4))))
                    c[nt][2 + e] = -1e30f;
            } else {
                c[nt][e] = -1e30f;
                c[nt][2 + e] = -1e30f;
            }
        }
    }

    // softmax across 4-lane row groups
    float mx1 = -1e30f, mx2 = -1e30f;
    #pragma unroll
    for (int nt = 0; nt < 8; ++nt) {
        mx1 = fmaxf(mx1, fmaxf(c[nt][0], c[nt][1]));
        mx2 = fmaxf(mx2, fmaxf(c[nt][2], c[nt][3]));
    }
    mx1 = fmaxf(mx1, __shfl_xor_sync(0xffffffffu, mx1, 1));
    mx1 = fmaxf(mx1, __shfl_xor_sync(0xffffffffu, mx1, 2));
    mx2 = fmaxf(mx2, __shfl_xor_sync(0xffffffffu, mx2, 1));
    mx2 = fmaxf(mx2, __shfl_xor_sync(0xffffffffu, mx2, 2));

    float sum1 = 0.f, sum2 = 0.f;
    #pragma unroll
    for (int nt = 0; nt < 8; ++nt) {
        c[nt][0] = __expf(c[nt][0] - mx1);
        c[nt][1] = __expf(c[nt][1] - mx1);
        c[nt][2] = __expf(c[nt][2] - mx2);
        c[nt][3] = __expf(c[nt][3] - mx2);
        sum1 += c[nt][0] + c[nt][1];
        sum2 += c[nt][2] + c[nt][3];
    }
    sum1 += __shfl_xor_sync(0xffffffffu, sum1, 1);
    sum1 += __shfl_xor_sync(0xffffffffu, sum1, 2);
    sum2 += __shfl_xor_sync(0xffffffffu, sum2, 1);
    sum2 += __shfl_xor_sync(0xffffffffu, sum2, 2);

    // P (unnormalized) -> smem, pair-interleaved j
    #pragma unroll
    for (int nt = 0; nt < 8; ++nt) {
        const int jc = nt * 8 + 2 * (lane & 3);
        Ps[r1 * PJ_P + pcol(jc)]     = f2tf(c[nt][0]);
        Ps[r1 * PJ_P + pcol(jc + 1)] = f2tf(c[nt][1]);
        Ps[r2 * PJ_P + pcol(jc)]     = f2tf(c[nt][2]);
        Ps[r2 * PJ_P + pcol(jc + 1)] = f2tf(c[nt][3]);
    }
    __syncwarp();

    // PV: 16x32 per warp, k = 64
    float o[4][4];
    #pragma unroll
    for (int nt = 0; nt < 4; ++nt)
        #pragma unroll
        for (int q = 0; q < 4; ++q) o[nt][q] = 0.f;
    #pragma unroll
    for (int kk = 0; kk < 8; ++kk) {
        const int k0 = kk * 8 + 2 * (lane & 3);
        const uint2 P1 = *(const uint2*)(Ps + r1 * PJ_P + k0);
        const uint2 P2 = *(const uint2*)(Ps + r2 * PJ_P + k0);
        const uint32_t ap[4] = {P1.x, P2.x, P1.y, P2.y};
        #pragma unroll
        for (int nt = 0; nt < 4; ++nt) {
            const uint2 B = *(const uint2*)(VT + (nt * 8 + (lane >> 2)) * PJ_P + k0);
            mma8(o[nt], ap, B);
        }
    }

    const float inv1 = 1.f / sum1, inv2 = 1.f / sum2;
    #pragma unroll
    for (int nt = 0; nt < 4; ++nt) {
        const int d = nt * 8 + 2 * (lane & 3);
        if (r1 < SEQ)
            *(float2*)(g_attn + (((size_t)b * NWIN + win) * SEQ + r1) * CH + head * HD + d) =
                make_float2(o[nt][0] * inv1, o[nt][1] * inv1);
        if (r2 < SEQ)
            *(float2*)(g_attn + (((size_t)b * NWIN + win) * SEQ + r2) * CH + head * HD + d) =
                make_float2(o[nt][2] * inv2, o[nt][3] * inv2);
    }
}

// ---------------------------------------------------------------------------
// Kernel 3: output projection + bias + inverse-roll scatter. grid (49,1,64).
// ---------------------------------------------------------------------------
__global__ __launch_bounds__(256, 2) void proj_mma_kernel(const float* __restrict__ w_out,
                                                          const float* __restrict__ b_out,
                                                          float* __restrict__ out) {
    extern __shared__ uint32_t sh[];
    uint32_t* As = sh;
    uint32_t* Bs = sh + 64 * PK;

    const int mtile = blockIdx.x, b = blockIdx.z;
    const int tid = threadIdx.x, lane = tid & 31, wid = tid >> 5;

    #pragma unroll
    for (int it = 0; it < 4; ++it) {
        const int idx = tid + 256 * it;
        const int row = idx >> 4, gb = (idx & 15) * 8;
        const float4* sp = (const float4*)(g_attn + ((size_t)b * MPB + mtile * 64 + row) * CH + gb);
        st_pairs(As + row * PK + gb, sp[0], sp[1]);
    }
    #pragma unroll
    for (int it = 0; it < 8; ++it) {
        const int idx = tid + 256 * it;
        const int row = idx >> 4, gb = (idx & 15) * 8;
        const float4* sp = (const float4*)(w_out + (size_t)row * CH + gb);
        st_pairs(Bs + row * PK + gb, sp[0], sp[1]);
    }
    __syncthreads();

    const int wm = wid & 1, wn = wid >> 1;
    const int m0 = wm * 32, n0 = wn * 32;

    float acc[2][4][4];
    #pragma unroll
    for (int mt = 0; mt < 2; ++mt)
        #pragma unroll
        for (int nt = 0; nt < 4; ++nt)
            #pragma unroll
            for (int q = 0; q < 4; ++q) acc[mt][nt][q] = 0.f;

    #pragma unroll
    for (int kk = 0; kk < 16; ++kk) {
        const int k0 = kk * 8 + 2 * (lane & 3);
        const uint32_t* ar = As + (m0 + (lane >> 2)) * PK + k0;
        const uint2 A10 = *(const uint2*)(ar);
        const uint2 A11 = *(const uint2*)(ar + 8 * PK);
        const uint2 A20 = *(const uint2*)(ar + 16 * PK);
        const uint2 A21 = *(const uint2*)(ar + 24 * PK);
        const uint32_t a0[4] = {A10.x, A11.x, A10.y, A11.y};
        const uint32_t a1[4] = {A20.x, A21.x, A20.y, A21.y};
        #pragma unroll
        for (int nt = 0; nt < 4; ++nt) {
            const uint2 B = *(const uint2*)(Bs + (n0 + nt * 8 + (lane >> 2)) * PK + k0);
            mma8(acc[0][nt], a0, B);
            mma8(acc[1][nt], a1, B);
        }
    }

    #pragma unroll
    for (int mt = 0; mt < 2; ++mt) {
        #pragma unroll
        for (int hh = 0; hh < 2; ++hh) {
            const int m = mtile * 64 + m0 + mt * 16 + hh * 8 + (lane >> 2);
            const int win = m / 49, s = m - win * 49;
            const int wr = win >> 3, wc = win & 7;
            const int i = s / 7, j = s - i * 7;
            int gh = wr * 7 + i + DISP; if (gh >= HW) gh -= HW;
            int gw = wc * 7 + j + DISP; if (gw >= HW) gw -= HW;
            float* orow = out + (((size_t)b * HW + gh) * HW + gw) * CH;
            #pragma unroll
            for (int nt = 0; nt < 4; ++nt) {
                const int n = n0 + nt * 8 + 2 * (lane & 3);
                float2 val = (hh == 0)
                    ? make_float2(acc[mt][nt][0], acc[mt][nt][1])
                    : make_float2(acc[mt][nt][2], acc[mt][nt][3]);
                val.x += __ldg(b_out + n);
                val.y += __ldg(b_out + n + 1);
                *(float2*)(orow + n) = val;
            }
        }
    }
}

extern "C" void kernel_launch(void* const* d_in, const int* in_sizes, int n_in,
                              void* d_out, int out_size) {
    const float* x      = (const float*)d_in[0];
    const float* w_qkv  = (const float*)d_in[1];
    const float* pos    = (const float*)d_in[2];
    const float* w_out  = (const float*)d_in[3];
    const float* b_out  = (const float*)d_in[4];
    float* out = (float*)d_out;

    cudaFuncSetAttribute(qkv_mma_kernel,  cudaFuncAttributeMaxDynamicSharedMemorySize, GEMM_SMEM);
    cudaFuncSetAttribute(proj_mma_kernel, cudaFuncAttributeMaxDynamicSharedMemorySize, GEMM_SMEM);

    qkv_mma_kernel<<<dim3(MT64, 3, BATCH), 256, GEMM_SMEM>>>(x, w_qkv);
    attn_mma_kernel<<<BATCH * NWIN * HEADS, 128>>>(pos);
    proj_mma_kernel<<<dim3(MT64, 1, BATCH), 256, GEMM_SMEM>>>(w_out, b_out, out);
}

// round 9
// speedup vs baseline: 5.0909x; 2.0990x over previous
#include <cuda_runtime.h>
#include <cuda_fp16.h>
#include <cstdint>

// Swin shifted-window attention, B=64, H=W=56, C=128, heads=4, hd=32, ws=7, shift=3.
// Round 9: fp16 mma (m16n8k16, fp32 accum) everywhere. fp16 scratch, preconverted
// weights, pair-interleaved k-layout -> all fragment loads are conflict-free LDS.64.

#define BATCH 64
#define HW    56
#define CH    128
#define NWIN  64
#define SEQ   49
#define HEADS 4
#define HD    32
#define DISP  3
#define MPB   3136        // windowed rows per batch (64*49)
#define MT64  49          // 3136/64
#define PKH   72          // gemm smem pitch (u32; 64 data + 8; 72 mod 32 = 8)
#define GEMM_SMEM ((64 + 128) * PKH * 4)   // 55296 B

#define KT_P  24          // attn K-tile pitch (16 data u32)
#define PJ_P  40          // attn V/P pitch (32 data u32)

// fp16 scratch, pair-interleaved within 16-k groups (u32 = half2)
__device__ uint32_t g_q[(size_t)BATCH*HEADS*NWIN*SEQ*16];
__device__ uint32_t g_k[(size_t)BATCH*HEADS*NWIN*SEQ*16];
__device__ uint32_t g_v[(size_t)BATCH*HEADS*NWIN*SEQ*16];
__device__ uint32_t g_attn[(size_t)BATCH*NWIN*SEQ*64];
__device__ uint32_t g_wqkv_h[384*64];
__device__ uint32_t g_wout_h[128*64];

__device__ __forceinline__ uint32_t f2h2(float a, float b) {
    __half2 h = __floats2half2_rn(a, b);
    return *(uint32_t*)&h;
}

__device__ __forceinline__ void mma16(float* c, const uint32_t* a, uint2 b) {
    asm volatile(
        "mma.sync.aligned.m16n8k16.row.col.f32.f16.f16.f32 "
        "{%0,%1,%2,%3}, {%4,%5,%6,%7}, {%8,%9}, {%0,%1,%2,%3};\n"
        : "+f"(c[0]), "+f"(c[1]), "+f"(c[2]), "+f"(c[3])
        : "r"(a[0]), "r"(a[1]), "r"(a[2]), "r"(a[3]), "r"(b.x), "r"(b.y));
}

// Convert 16 consecutive k floats (f0..f3) to 8 u32 half2, pair-interleaved:
// positions 0..7 hold pairs [0,4,1,5,2,6,3,7].
__device__ __forceinline__ void stg16(uint32_t* dst, float4 f0, float4 f1, float4 f2, float4 f3) {
    *(uint4*)(dst)     = make_uint4(f2h2(f0.x,f0.y), f2h2(f2.x,f2.y), f2h2(f0.z,f0.w), f2h2(f2.z,f2.w));
    *(uint4*)(dst + 4) = make_uint4(f2h2(f1.x,f1.y), f2h2(f3.x,f3.y), f2h2(f1.z,f1.w), f2h2(f3.z,f3.w));
}

// ---------------------------------------------------------------------------
// Kernel 0: one-time weight conversion (per launch) into interleaved fp16.
// ---------------------------------------------------------------------------
__global__ __launch_bounds__(256) void wconv_kernel(const float* __restrict__ w_qkv,
                                                    const float* __restrict__ w_out) {
    const int idx = blockIdx.x * 256 + threadIdx.x;   // 4096 total
    const float* src;
    uint32_t* dst;
    int row, g;
    if (idx < 3072) { row = idx >> 3; g = idx & 7; src = w_qkv; dst = g_wqkv_h; }
    else            { int j = idx - 3072; row = j >> 3; g = j & 7; src = w_out; dst = g_wout_h; }
    const float4* sp = (const float4*)(src + (size_t)row * CH + g * 16);
    stg16(dst + row * 64 + g * 8, sp[0], sp[1], sp[2], sp[3]);
}

// ---------------------------------------------------------------------------
// Kernel 1: fused roll + QKV projection. grid (49, 3, 64), block 256 = 8 warps
// (2m x 4n), warp tile 32x32, K=128 as 8 k16-steps.
// ---------------------------------------------------------------------------
__global__ __launch_bounds__(256, 2) void qkv_mma_kernel(const float* __restrict__ x) {
    extern __shared__ uint32_t sh[];
    uint32_t* As = sh;              // [64][PKH]
    uint32_t* Bs = sh + 64 * PKH;   // [128][PKH]

    const int mtile = blockIdx.x, ntile = blockIdx.y, b = blockIdx.z;
    const int tid = threadIdx.x, lane = tid & 31, wid = tid >> 5;

    // A: 64 rows x 128k (fp32 -> fp16 interleaved). 512 (row, 16k-group) units.
    #pragma unroll
    for (int it = 0; it < 2; ++it) {
        const int idx = tid + 256 * it;
        const int row = idx >> 3, g = idx & 7;
        const int m = mtile * 64 + row;
        const int win = m / 49, s = m - win * 49;
        const int wr = win >> 3, wc = win & 7;
        const int i = s / 7, j = s - i * 7;
        int gh = wr * 7 + i + DISP; if (gh >= HW) gh -= HW;
        int gw = wc * 7 + j + DISP; if (gw >= HW) gw -= HW;
        const float4* sp = (const float4*)(x + (((size_t)b * HW + gh) * HW + gw) * CH + g * 16);
        stg16(As + row * PKH + g * 8, sp[0], sp[1], sp[2], sp[3]);
    }
    // B: flat copy of preconverted weights (already interleaved).
    #pragma unroll
    for (int it = 0; it < 8; ++it) {
        const int idx = tid + 256 * it;             // 2048 uint4
        const int row = idx >> 4, c4 = idx & 15;
        *(uint4*)(Bs + row * PKH + c4 * 4) =
            ((const uint4*)(g_wqkv_h + ((size_t)(ntile * 128 + row)) * 64))[c4];
    }
    __syncthreads();

    const int wm = wid & 1, wn = wid >> 1;
    const int m0 = wm * 32, n0 = wn * 32;

    float acc[2][4][4];
    #pragma unroll
    for (int mt = 0; mt < 2; ++mt)
        #pragma unroll
        for (int nt = 0; nt < 4; ++nt)
            #pragma unroll
            for (int q = 0; q < 4; ++q) acc[mt][nt][q] = 0.f;

    #pragma unroll
    for (int kk = 0; kk < 8; ++kk) {
        const int k0 = kk * 8 + 2 * (lane & 3);
        const uint32_t* ar = As + (m0 + (lane >> 2)) * PKH + k0;
        const uint2 A10 = *(const uint2*)(ar);
        const uint2 A11 = *(const uint2*)(ar + 8 * PKH);
        const uint2 A20 = *(const uint2*)(ar + 16 * PKH);
        const uint2 A21 = *(const uint2*)(ar + 24 * PKH);
        const uint32_t a0[4] = {A10.x, A11.x, A10.y, A11.y};
        const uint32_t a1[4] = {A20.x, A21.x, A20.y, A21.y};
        #pragma unroll
        for (int nt = 0; nt < 4; ++nt) {
            const uint2 B = *(const uint2*)(Bs + (n0 + nt * 8 + (lane >> 2)) * PKH + k0);
            mma16(acc[0][nt], a0, B);
            mma16(acc[1][nt], a1, B);
        }
    }

    // epilogue: pack to fp16 half2, interleaved pair positions; q pre-scaled by 0.5
    uint32_t* gout = (ntile == 0) ? g_q : (ntile == 1) ? g_k : g_v;
    const float sc = (ntile == 0) ? 0.5f : 1.0f;
    const int c = lane & 3;
    #pragma unroll
    for (int mt = 0; mt < 2; ++mt) {
        #pragma unroll
        for (int hh = 0; hh < 2; ++hh) {
            const int m = mtile * 64 + m0 + mt * 16 + hh * 8 + (lane >> 2);
            const int win = m / 49, s = m - win * 49;
            const size_t rb = ((((size_t)b * HEADS + wn) * NWIN + win) * SEQ + s) * 16;
            #pragma unroll
            for (int nt = 0; nt < 4; ++nt) {
                const int idx = 8 * (nt >> 1) + 2 * c + (nt & 1);
                const float v0 = (hh == 0) ? acc[mt][nt][0] : acc[mt][nt][2];
                const float v1 = (hh == 0) ? acc[mt][nt][1] : acc[mt][nt][3];
                gout[rb + idx] = f2h2(sc * v0, sc * v1);
            }
        }
    }
}

// ---------------------------------------------------------------------------
// Kernel 2: fp16 mma attention. One block per (b, win, head), 128 threads.
// ---------------------------------------------------------------------------
__global__ __launch_bounds__(128, 4) void attn_mma_kernel(const float* __restrict__ pos) {
    __shared__ uint32_t Kt[64 * KT_P];   // [n][k16 interleaved]
    __shared__ uint32_t VT[32 * PJ_P];   // [d][j pairs interleaved]
    __shared__ uint32_t Ps[64 * PJ_P];   // [i][j pairs interleaved]
    __shared__ float    ps[172];

    const int blk  = blockIdx.x;
    const int head = blk & 3;
    const int win  = (blk >> 2) & 63;
    const int b    = blk >> 8;
    const int tid  = threadIdx.x, lane = tid & 31, w = tid >> 5;
    const size_t baseu = (((size_t)b * HEADS + head) * NWIN + win) * SEQ * 16;

    // K -> Kt: flat copy (g_k already interleaved); rows >= SEQ zero.
    {
        const int r = tid >> 1, h = tid & 1;
        uint4* dst = (uint4*)(Kt + r * KT_P + h * 8);
        if (r < SEQ) {
            const uint4* sp = (const uint4*)(g_k + baseu + r * 16 + h * 8);
            dst[0] = sp[0]; dst[1] = sp[1];
        } else {
            dst[0] = make_uint4(0,0,0,0); dst[1] = make_uint4(0,0,0,0);
        }
    }
    // V -> VT transposed via half extraction (1024 (d, jpair) units).
    #pragma unroll
    for (int it = 0; it < 8; ++it) {
        const int idx = tid + 128 * it;
        const int d = idx & 31, jp = idx >> 5;
        const int dp = d >> 1;
        const int vpos = (dp & 8) + 2 * (dp & 3) + ((dp >> 2) & 1);
        const int j0 = 2 * jp, j1 = 2 * jp + 1;
        uint32_t u0 = (j0 < SEQ) ? g_v[baseu + j0 * 16 + vpos] : 0u;
        uint32_t u1 = (j1 < SEQ) ? g_v[baseu + j1 * 16 + vpos] : 0u;
        const uint32_t h0 = (d & 1) ? (u0 >> 16) : (u0 & 0xFFFFu);
        const uint32_t h1 = (d & 1) ? (u1 >> 16) : (u1 & 0xFFFFu);
        const int ppos = (jp & 24) + 2 * (jp & 3) + ((jp >> 2) & 1);
        VT[d * PJ_P + ppos] = h0 | (h1 << 16);
    }
    for (int idx = tid; idx < 169; idx += 128) ps[idx] = pos[idx];
    __syncthreads();

    // Q fragments from gmem (pre-scaled, interleaved -> LDG.64 per k-step)
    const int r1 = 16 * w + (lane >> 2), r2 = r1 + 8;
    const int c = lane & 3;
    uint32_t a[2][4];
    #pragma unroll
    for (int kk = 0; kk < 2; ++kk) {
        uint2 q1 = make_uint2(0, 0), q2 = make_uint2(0, 0);
        if (r1 < SEQ) q1 = *(const uint2*)(g_q + baseu + r1 * 16 + kk * 8 + 2 * c);
        if (r2 < SEQ) q2 = *(const uint2*)(g_q + baseu + r2 * 16 + kk * 8 + 2 * c);
        a[kk][0] = q1.x; a[kk][1] = q2.x; a[kk][2] = q1.y; a[kk][3] = q2.y;
    }

    // scores 16x64 per warp (2 k16-steps)
    float cc[8][4];
    #pragma unroll
    for (int nt = 0; nt < 8; ++nt)
        #pragma unroll
        for (int q = 0; q < 4; ++q) cc[nt][q] = 0.f;
    #pragma unroll
    for (int kk = 0; kk < 2; ++kk) {
        const int k0 = kk * 8 + 2 * c;
        #pragma unroll
        for (int nt = 0; nt < 8; ++nt) {
            const uint2 B = *(const uint2*)(Kt + (nt * 8 + (lane >> 2)) * KT_P + k0);
            mma16(cc[nt], a[kk], B);
        }
    }

    // bias + shift mask
    const int wr = win >> 3, wc = win & 7;
    const bool mU = (wr == 7), mL = (wc == 7);
    const int ic1 = (r1 < SEQ) ? r1 : 48, ic2 = (r2 < SEQ) ? r2 : 48;
    const int xi1 = ic1 / 7, yi1 = ic1 - 7 * xi1;
    const int xi2 = ic2 / 7, yi2 = ic2 - 7 * xi2;
    #pragma unroll
    for (int nt = 0; nt < 8; ++nt) {
        #pragma unroll
        for (int e = 0; e < 2; ++e) {
            const int jj = nt * 8 + 2 * c + e;
            if (jj < SEQ) {
                const int xj = jj / 7, yj = jj - 7 * xj;
                cc[nt][e]     += ps[(xj - xi1 + 6) * 13 + (yj - yi1 + 6)];
                cc[nt][2 + e] += ps[(xj - xi2 + 6) * 13 + (yj - yi2 + 6)];
                if ((mU && ((xi1 >= 4) != (xj >= 4))) || (mL && ((yi1 >= 4) != (yj >= 4))))
                    cc[nt][e] = -1e30f;
                if ((mU && ((xi2 >= 4) != (xj >= 4))) || (mL && ((yi2 >= 4) != (yj >= 4))))
                    cc[nt][2 + e] = -1e30f;
            } else {
                cc[nt][e] = -1e30f;
                cc[nt][2 + e] = -1e30f;
            }
        }
    }

    // softmax across 4-lane row groups
    float mx1 = -1e30f, mx2 = -1e30f;
    #pragma unroll
    for (int nt = 0; nt < 8; ++nt) {
        mx1 = fmaxf(mx1, fmaxf(cc[nt][0], cc[nt][1]));
        mx2 = fmaxf(mx2, fmaxf(cc[nt][2], cc[nt][3]));
    }
    mx1 = fmaxf(mx1, __shfl_xor_sync(0xffffffffu, mx1, 1));
    mx1 = fmaxf(mx1, __shfl_xor_sync(0xffffffffu, mx1, 2));
    mx2 = fmaxf(mx2, __shfl_xor_sync(0xffffffffu, mx2, 1));
    mx2 = fmaxf(mx2, __shfl_xor_sync(0xffffffffu, mx2, 2));

    float sum1 = 0.f, sum2 = 0.f;
    #pragma unroll
    for (int nt = 0; nt < 8; ++nt) {
        cc[nt][0] = __expf(cc[nt][0] - mx1);
        cc[nt][1] = __expf(cc[nt][1] - mx1);
        cc[nt][2] = __expf(cc[nt][2] - mx2);
        cc[nt][3] = __expf(cc[nt][3] - mx2);
        sum1 += cc[nt][0] + cc[nt][1];
        sum2 += cc[nt][2] + cc[nt][3];
    }
    sum1 += __shfl_xor_sync(0xffffffffu, sum1, 1);
    sum1 += __shfl_xor_sync(0xffffffffu, sum1, 2);
    sum2 += __shfl_xor_sync(0xffffffffu, sum2, 1);
    sum2 += __shfl_xor_sync(0xffffffffu, sum2, 2);

    // P (unnormalized) -> Ps, interleaved
    #pragma unroll
    for (int nt = 0; nt < 8; ++nt) {
        const int ppos = 8 * (nt >> 1) + 2 * c + (nt & 1);
        Ps[r1 * PJ_P + ppos] = f2h2(cc[nt][0], cc[nt][1]);
        Ps[r2 * PJ_P + ppos] = f2h2(cc[nt][2], cc[nt][3]);
    }
    __syncwarp();

    // PV: 16x32 per warp, 4 k16-steps
    float o[4][4];
    #pragma unroll
    for (int nt = 0; nt < 4; ++nt)
        #pragma unroll
        for (int q = 0; q < 4; ++q) o[nt][q] = 0.f;
    #pragma unroll
    for (int kk = 0; kk < 4; ++kk) {
        const int k0 = kk * 8 + 2 * c;
        const uint2 P1 = *(const uint2*)(Ps + r1 * PJ_P + k0);
        const uint2 P2 = *(const uint2*)(Ps + r2 * PJ_P + k0);
        const uint32_t ap[4] = {P1.x, P2.x, P1.y, P2.y};
        #pragma unroll
        for (int nt = 0; nt < 4; ++nt) {
            const uint2 B = *(const uint2*)(VT + (nt * 8 + (lane >> 2)) * PJ_P + k0);
            mma16(o[nt], ap, B);
        }
    }

    const float inv1 = 1.f / sum1, inv2 = 1.f / sum2;
    #pragma unroll
    for (int nt = 0; nt < 4; ++nt) {
        const int idx = 8 * (nt >> 1) + 2 * c + (nt & 1);
        if (r1 < SEQ)
            g_attn[(((size_t)b * NWIN + win) * SEQ + r1) * 64 + head * 16 + idx] =
                f2h2(o[nt][0] * inv1, o[nt][1] * inv1);
        if (r2 < SEQ)
            g_attn[(((size_t)b * NWIN + win) * SEQ + r2) * 64 + head * 16 + idx] =
                f2h2(o[nt][2] * inv2, o[nt][3] * inv2);
    }
}

// ---------------------------------------------------------------------------
// Kernel 3: output projection + bias + inverse-roll scatter. grid (49,1,64).
// ---------------------------------------------------------------------------
__global__ __launch_bounds__(256, 2) void proj_mma_kernel(const float* __restrict__ b_out,
                                                          float* __restrict__ out) {
    extern __shared__ uint32_t sh[];
    uint32_t* As = sh;
    uint32_t* Bs = sh + 64 * PKH;

    const int mtile = blockIdx.x, b = blockIdx.z;
    const int tid = threadIdx.x, lane = tid & 31, wid = tid >> 5;

    // A: flat copy from g_attn (already fp16 interleaved). 1024 uint4.
    #pragma unroll
    for (int it = 0; it < 4; ++it) {
        const int idx = tid + 256 * it;
        const int row = idx >> 4, c4 = idx & 15;
        *(uint4*)(As + row * PKH + c4 * 4) =
            ((const uint4*)(g_attn + ((size_t)b * MPB + mtile * 64 + row) * 64))[c4];
    }
    // B: flat copy of preconverted w_out.
    #pragma unroll
    for (int it = 0; it < 8; ++it) {
        const int idx = tid + 256 * it;
        const int row = idx >> 4, c4 = idx & 15;
        *(uint4*)(Bs + row * PKH + c4 * 4) = ((const uint4*)(g_wout_h + (size_t)row * 64))[c4];
    }
    __syncthreads();

    const int wm = wid & 1, wn = wid >> 1;
    const int m0 = wm * 32, n0 = wn * 32;

    float acc[2][4][4];
    #pragma unroll
    for (int mt = 0; mt < 2; ++mt)
        #pragma unroll
        for (int nt = 0; nt < 4; ++nt)
            #pragma unroll
            for (int q = 0; q < 4; ++q) acc[mt][nt][q] = 0.f;

    #pragma unroll
    for (int kk = 0; kk < 8; ++kk) {
        const int k0 = kk * 8 + 2 * (lane & 3);
        const uint32_t* ar = As + (m0 + (lane >> 2)) * PKH + k0;
        const uint2 A10 = *(const uint2*)(ar);
        const uint2 A11 = *(const uint2*)(ar + 8 * PKH);
        const uint2 A20 = *(const uint2*)(ar + 16 * PKH);
        const uint2 A21 = *(const uint2*)(ar + 24 * PKH);
        const uint32_t a0[4] = {A10.x, A11.x, A10.y, A11.y};
        const uint32_t a1[4] = {A20.x, A21.x, A20.y, A21.y};
        #pragma unroll
        for (int nt = 0; nt < 4; ++nt) {
            const uint2 B = *(const uint2*)(Bs + (n0 + nt * 8 + (lane >> 2)) * PKH + k0);
            mma16(acc[0][nt], a0, B);
            mma16(acc[1][nt], a1, B);
        }
    }

    #pragma unroll
    for (int mt = 0; mt < 2; ++mt) {
        #pragma unroll
        for (int hh = 0; hh < 2; ++hh) {
            const int m = mtile * 64 + m0 + mt * 16 + hh * 8 + (lane >> 2);
            const int win = m / 49, s = m - win * 49;
            const int wr = win >> 3, wc = win & 7;
            const int i = s / 7, j = s - i * 7;
            int gh = wr * 7 + i + DISP; if (gh >= HW) gh -= HW;
            int gw = wc * 7 + j + DISP; if (gw >= HW) gw -= HW;
            float* orow = out + (((size_t)b * HW + gh) * HW + gw) * CH;
            #pragma unroll
            for (int nt = 0; nt < 4; ++nt) {
                const int n = n0 + nt * 8 + 2 * (lane & 3);
                float2 val = (hh == 0)
                    ? make_float2(acc[mt][nt][0], acc[mt][nt][1])
                    : make_float2(acc[mt][nt][2], acc[mt][nt][3]);
                val.x += __ldg(b_out + n);
                val.y += __ldg(b_out + n + 1);
                *(float2*)(orow + n) = val;
            }
        }
    }
}

extern "C" void kernel_launch(void* const* d_in, const int* in_sizes, int n_in,
                              void* d_out, int out_size) {
    const float* x      = (const float*)d_in[0];
    const float* w_qkv  = (const float*)d_in[1];
    const float* pos    = (const float*)d_in[2];
    const float* w_out  = (const float*)d_in[3];
    const float* b_out  = (const float*)d_in[4];
    float* out = (float*)d_out;

    cudaFuncSetAttribute(qkv_mma_kernel,  cudaFuncAttributeMaxDynamicSharedMemorySize, GEMM_SMEM);
    cudaFuncSetAttribute(proj_mma_kernel, cudaFuncAttributeMaxDynamicSharedMemorySize, GEMM_SMEM);

    wconv_kernel<<<16, 256>>>(w_qkv, w_out);
    qkv_mma_kernel<<<dim3(MT64, 3, BATCH), 256, GEMM_SMEM>>>(x);
    attn_mma_kernel<<<BATCH * NWIN * HEADS, 128>>>(pos);
    proj_mma_kernel<<<dim3(MT64, 1, BATCH), 256, GEMM_SMEM>>>(b_out, out);
}

// round 11
// speedup vs baseline: 5.8931x; 1.1576x over previous
#include <cuda_runtime.h>
#include <cuda_fp16.h>
#include <cstdint>

// Swin shifted-window attention, B=64, H=W=56, C=128, heads=4, hd=32, ws=7, shift=3.
// Round 10: fp16 mma; qkv gathers A once + cp.async double-buffered B chunks;
// proj uses cp.async for both tiles. attn unchanged from R9.

#define BATCH 64
#define HW    56
#define CH    128
#define NWIN  64
#define SEQ   49
#define HEADS 4
#define HD    32
#define DISP  3
#define MPB   3136
#define MT64  49
#define PKH   72          // smem pitch (u32), 72 mod 32 = 8 -> conflict-free
#define QKV_SMEM ((64 + 2 * 128) * PKH * 4)   // 92160 B -> 2 CTA/SM
#define PROJ_SMEM ((64 + 128) * PKH * 4)      // 55296 B

#define KT_P  24
#define PJ_P  40

// fp16 scratch, pair-interleaved within 16-k groups (u32 = half2)
__device__ uint32_t g_q[(size_t)BATCH*HEADS*NWIN*SEQ*16];
__device__ uint32_t g_k[(size_t)BATCH*HEADS*NWIN*SEQ*16];
__device__ uint32_t g_v[(size_t)BATCH*HEADS*NWIN*SEQ*16];
__device__ uint32_t g_attn[(size_t)BATCH*NWIN*SEQ*64];
__device__ uint32_t g_wqkv_h[384*64];
__device__ uint32_t g_wout_h[128*64];

__device__ __forceinline__ uint32_t f2h2(float a, float b) {
    __half2 h = __floats2half2_rn(a, b);
    return *(uint32_t*)&h;
}
__device__ __forceinline__ void mma16(float* c, const uint32_t* a, uint2 b) {
    asm volatile(
        "mma.sync.aligned.m16n8k16.row.col.f32.f16.f16.f32 "
        "{%0,%1,%2,%3}, {%4,%5,%6,%7}, {%8,%9}, {%0,%1,%2,%3};\n"
        : "+f"(c[0]), "+f"(c[1]), "+f"(c[2]), "+f"(c[3])
        : "r"(a[0]), "r"(a[1]), "r"(a[2]), "r"(a[3]), "r"(b.x), "r"(b.y));
}
__device__ __forceinline__ void stg16(uint32_t* dst, float4 f0, float4 f1, float4 f2, float4 f3) {
    *(uint4*)(dst)     = make_uint4(f2h2(f0.x,f0.y), f2h2(f2.x,f2.y), f2h2(f0.z,f0.w), f2h2(f2.z,f2.w));
    *(uint4*)(dst + 4) = make_uint4(f2h2(f1.x,f1.y), f2h2(f3.x,f3.y), f2h2(f1.z,f1.w), f2h2(f3.z,f3.w));
}

__device__ __forceinline__ uint32_t smem_u32(const void* p) {
    return (uint32_t)__cvta_generic_to_shared(p);
}
__device__ __forceinline__ void cp_async16(uint32_t dst, const void* src) {
    asm volatile("cp.async.cg.shared.global [%0], [%1], 16;" :: "r"(dst), "l"(src) : "memory");
}
__device__ __forceinline__ void cp_commit() {
    asm volatile("cp.async.commit_group;" ::: "memory");
}
template <int N>
__device__ __forceinline__ void cp_wait() {
    asm volatile("cp.async.wait_group %0;" :: "n"(N) : "memory");
}

// ---------------------------------------------------------------------------
// Kernel 0: one-time weight conversion into interleaved fp16.
// ---------------------------------------------------------------------------
__global__ __launch_bounds__(256) void wconv_kernel(const float* __restrict__ w_qkv,
                                                    const float* __restrict__ w_out) {
    const int idx = blockIdx.x * 256 + threadIdx.x;   // 4096 total
    const float* src;
    uint32_t* dst;
    int row, g;
    if (idx < 3072) { row = idx >> 3; g = idx & 7; src = w_qkv; dst = g_wqkv_h; }
    else            { int j = idx - 3072; row = j >> 3; g = j & 7; src = w_out; dst = g_wout_h; }
    const float4* sp = (const float4*)(src + (size_t)row * CH + g * 16);
    stg16(dst + row * 64 + g * 8, sp[0], sp[1], sp[2], sp[3]);
}

// ---------------------------------------------------------------------------
// Kernel 1: fused roll + QKV projection. grid (49, 1, 64), block 256 = 8 warps.
// A gathered once; 3 weight chunks double-buffered via cp.async.
// ---------------------------------------------------------------------------
__global__ __launch_bounds__(256, 2) void qkv_mma_kernel(const float* __restrict__ x) {
    extern __shared__ uint32_t sh[];
    uint32_t* As = sh;                    // [64][PKH]
    uint32_t* Bs0 = sh + 64 * PKH;        // [128][PKH] buffer 0
    uint32_t* Bs1 = Bs0 + 128 * PKH;      // [128][PKH] buffer 1

    const int mtile = blockIdx.x, b = blockIdx.z;
    const int tid = threadIdx.x, lane = tid & 31, wid = tid >> 5;

    // prefetch B chunk 0 (already fp16 interleaved in g_wqkv_h)
    {
        uint32_t* Bd = Bs0;
        #pragma unroll
        for (int it = 0; it < 8; ++it) {
            const int idx = tid + 256 * it;
            const int row = idx >> 4, c4 = idx & 15;
            cp_async16(smem_u32(Bd + row * PKH + c4 * 4),
                       g_wqkv_h + (size_t)row * 64 + c4 * 4);
        }
        cp_commit();
    }

    // A: 64 rows x 128k, rolled-window gather, fp32 -> fp16 interleaved (once).
    #pragma unroll
    for (int it = 0; it < 2; ++it) {
        const int idx = tid + 256 * it;
        const int row = idx >> 3, g = idx & 7;
        const int m = mtile * 64 + row;
        const int win = m / 49, s = m - win * 49;
        const int wr = win >> 3, wc = win & 7;
        const int i = s / 7, j = s - i * 7;
        int gh = wr * 7 + i + DISP; if (gh >= HW) gh -= HW;
        int gw = wc * 7 + j + DISP; if (gw >= HW) gw -= HW;
        const float4* sp = (const float4*)(x + (((size_t)b * HW + gh) * HW + gw) * CH + g * 16);
        stg16(As + row * PKH + g * 8, sp[0], sp[1], sp[2], sp[3]);
    }

    const int wm = wid & 1, wn = wid >> 1;
    const int m0 = wm * 32, n0 = wn * 32;
    const int c = lane & 3;

    #pragma unroll
    for (int chunk = 0; chunk < 3; ++chunk) {
        uint32_t* Bcur = (chunk & 1) ? Bs1 : Bs0;
        // prefetch next chunk into the other buffer (safe: it was consumed
        // in chunk-2 iterations ago; first-iteration other-buffer is fresh).
        if (chunk < 2) {
            uint32_t* Bnext = (chunk & 1) ? Bs0 : Bs1;
            #pragma unroll
            for (int it = 0; it < 8; ++it) {
                const int idx = tid + 256 * it;
                const int row = idx >> 4, c4 = idx & 15;
                cp_async16(smem_u32(Bnext + row * PKH + c4 * 4),
                           g_wqkv_h + ((size_t)(chunk + 1) * 128 + row) * 64 + c4 * 4);
            }
            cp_commit();
            cp_wait<1>();
        } else {
            cp_wait<0>();
        }
        __syncthreads();

        float acc[2][4][4];
        #pragma unroll
        for (int mt = 0; mt < 2; ++mt)
            #pragma unroll
            for (int nt = 0; nt < 4; ++nt)
                #pragma unroll
                for (int q = 0; q < 4; ++q) acc[mt][nt][q] = 0.f;

        #pragma unroll
        for (int kk = 0; kk < 8; ++kk) {
            const int k0 = kk * 8 + 2 * c;
            const uint32_t* ar = As + (m0 + (lane >> 2)) * PKH + k0;
            const uint2 A10 = *(const uint2*)(ar);
            const uint2 A11 = *(const uint2*)(ar + 8 * PKH);
            const uint2 A20 = *(const uint2*)(ar + 16 * PKH);
            const uint2 A21 = *(const uint2*)(ar + 24 * PKH);
            const uint32_t a0[4] = {A10.x, A11.x, A10.y, A11.y};
            const uint32_t a1[4] = {A20.x, A21.x, A20.y, A21.y};
            #pragma unroll
            for (int nt = 0; nt < 4; ++nt) {
                const uint2 B = *(const uint2*)(Bcur + (n0 + nt * 8 + (lane >> 2)) * PKH + k0);
                mma16(acc[0][nt], a0, B);
                mma16(acc[1][nt], a1, B);
            }
        }

        uint32_t* gout = (chunk == 0) ? g_q : (chunk == 1) ? g_k : g_v;
        const float sc = (chunk == 0) ? 0.5f : 1.0f;
        #pragma unroll
        for (int mt = 0; mt < 2; ++mt) {
            #pragma unroll
            for (int hh = 0; hh < 2; ++hh) {
                const int m = mtile * 64 + m0 + mt * 16 + hh * 8 + (lane >> 2);
                const int win = m / 49, s = m - win * 49;
                const size_t rb = ((((size_t)b * HEADS + wn) * NWIN + win) * SEQ + s) * 16;
                #pragma unroll
                for (int nt = 0; nt < 4; ++nt) {
                    const int idx = 8 * (nt >> 1) + 2 * c + (nt & 1);
                    const float v0 = (hh == 0) ? acc[mt][nt][0] : acc[mt][nt][2];
                    const float v1 = (hh == 0) ? acc[mt][nt][1] : acc[mt][nt][3];
                    gout[rb + idx] = f2h2(sc * v0, sc * v1);
                }
            }
        }
        __syncthreads();   // all warps done with Bcur before it is refilled
    }
}

// ---------------------------------------------------------------------------
// Kernel 2: fp16 mma attention (unchanged from R9).
// ---------------------------------------------------------------------------
__global__ __launch_bounds__(128, 4) void attn_mma_kernel(const float* __restrict__ pos) {
    __shared__ uint32_t Kt[64 * KT_P];
    __shared__ uint32_t VT[32 * PJ_P];
    __shared__ uint32_t Ps[64 * PJ_P];
    __shared__ float    ps[172];

    const int blk  = blockIdx.x;
    const int head = blk & 3;
    const int win  = (blk >> 2) & 63;
    const int b    = blk >> 8;
    const int tid  = threadIdx.x, lane = tid & 31, w = tid >> 5;
    const size_t baseu = (((size_t)b * HEADS + head) * NWIN + win) * SEQ * 16;

    {
        const int r = tid >> 1, h = tid & 1;
        uint4* dst = (uint4*)(Kt + r * KT_P + h * 8);
        if (r < SEQ) {
            const uint4* sp = (const uint4*)(g_k + baseu + r * 16 + h * 8);
            dst[0] = sp[0]; dst[1] = sp[1];
        } else {
            dst[0] = make_uint4(0,0,0,0); dst[1] = make_uint4(0,0,0,0);
        }
    }
    #pragma unroll
    for (int it = 0; it < 8; ++it) {
        const int idx = tid + 128 * it;
        const int d = idx & 31, jp = idx >> 5;
        const int dp = d >> 1;
        const int vpos = (dp & 8) + 2 * (dp & 3) + ((dp >> 2) & 1);
        const int j0 = 2 * jp, j1 = 2 * jp + 1;
        uint32_t u0 = (j0 < SEQ) ? g_v[baseu + j0 * 16 + vpos] : 0u;
        uint32_t u1 = (j1 < SEQ) ? g_v[baseu + j1 * 16 + vpos] : 0u;
        const uint32_t h0 = (d & 1) ? (u0 >> 16) : (u0 & 0xFFFFu);
        const uint32_t h1 = (d & 1) ? (u1 >> 16) : (u1 & 0xFFFFu);
        const int ppos = (jp & 24) + 2 * (jp & 3) + ((jp >> 2) & 1);
        VT[d * PJ_P + ppos] = h0 | (h1 << 16);
    }
    for (int idx = tid; idx < 169; idx += 128) ps[idx] = pos[idx];
    __syncthreads();

    const int r1 = 16 * w + (lane >> 2), r2 = r1 + 8;
    const int c = lane & 3;
    uint32_t a[2][4];
    #pragma unroll
    for (int kk = 0; kk < 2; ++kk) {
        uint2 q1 = make_uint2(0, 0), q2 = make_uint2(0, 0);
        if (r1 < SEQ) q1 = *(const uint2*)(g_q + baseu + r1 * 16 + kk * 8 + 2 * c);
        if (r2 < SEQ) q2 = *(const uint2*)(g_q + baseu + r2 * 16 + kk * 8 + 2 * c);
        a[kk][0] = q1.x; a[kk][1] = q2.x; a[kk][2] = q1.y; a[kk][3] = q2.y;
    }

    float cc[8][4];
    #pragma unroll
    for (int nt = 0; nt < 8; ++nt)
        #pragma unroll
        for (int q = 0; q < 4; ++q) cc[nt][q] = 0.f;
    #pragma unroll
    for (int kk = 0; kk < 2; ++kk) {
        const int k0 = kk * 8 + 2 * c;
        #pragma unroll
        for (int nt = 0; nt < 8; ++nt) {
            const uint2 B = *(const uint2*)(Kt + (nt * 8 + (lane >> 2)) * KT_P + k0);
            mma16(cc[nt], a[kk], B);
        }
    }

    const int wr = win >> 3, wc = win & 7;
    const bool mU = (wr == 7), mL = (wc == 7);
    const int ic1 = (r1 < SEQ) ? r1 : 48, ic2 = (r2 < SEQ) ? r2 : 48;
    const int xi1 = ic1 / 7, yi1 = ic1 - 7 * xi1;
    const int xi2 = ic2 / 7, yi2 = ic2 - 7 * xi2;
    #pragma unroll
    for (int nt = 0; nt < 8; ++nt) {
        #pragma unroll
        for (int e = 0; e < 2; ++e) {
            const int jj = nt * 8 + 2 * c + e;
            if (jj < SEQ) {
                const int xj = jj / 7, yj = jj - 7 * xj;
                cc[nt][e]     += ps[(xj - xi1 + 6) * 13 + (yj - yi1 + 6)];
                cc[nt][2 + e] += ps[(xj - xi2 + 6) * 13 + (yj - yi2 + 6)];
                if ((mU && ((xi1 >= 4) != (xj >= 4))) || (mL && ((yi1 >= 4) != (yj >= 4))))
                    cc[nt][e] = -1e30f;
                if ((mU && ((xi2 >= 4) != (xj >= 4))) || (mL && ((yi2 >= 4) != (yj >= 4))))
                    cc[nt][2 + e] = -1e30f;
            } else {
                cc[nt][e] = -1e30f;
                cc[nt][2 + e] = -1e30f;
            }
        }
    }

    float mx1 = -1e30f, mx2 = -1e30f;
    #pragma unroll
    for (int nt = 0; nt < 8; ++nt) {
        mx1 = fmaxf(mx1, fmaxf(cc[nt][0], cc[nt][1]));
        mx2 = fmaxf(mx2, fmaxf(cc[nt][2], cc[nt][3]));
    }
    mx1 = fmaxf(mx1, __shfl_xor_sync(0xffffffffu, mx1, 1));
    mx1 = fmaxf(mx1, __shfl_xor_sync(0xffffffffu, mx1, 2));
    mx2 = fmaxf(mx2, __shfl_xor_sync(0xffffffffu, mx2, 1));
    mx2 = fmaxf(mx2, __shfl_xor_sync(0xffffffffu, mx2, 2));

    float sum1 = 0.f, sum2 = 0.f;
    #pragma unroll
    for (int nt = 0; nt < 8; ++nt) {
        cc[nt][0] = __expf(cc[nt][0] - mx1);
        cc[nt][1] = __expf(cc[nt][1] - mx1);
        cc[nt][2] = __expf(cc[nt][2] - mx2);
        cc[nt][3] = __expf(cc[nt][3] - mx2);
        sum1 += cc[nt][0] + cc[nt][1];
        sum2 += cc[nt][2] + cc[nt][3];
    }
    sum1 += __shfl_xor_sync(0xffffffffu, sum1, 1);
    sum1 += __shfl_xor_sync(0xffffffffu, sum1, 2);
    sum2 += __shfl_xor_sync(0xffffffffu, sum2, 1);
    sum2 += __shfl_xor_sync(0xffffffffu, sum2, 2);

    #pragma unroll
    for (int nt = 0; nt < 8; ++nt) {
        const int ppos = 8 * (nt >> 1) + 2 * c + (nt & 1);
        Ps[r1 * PJ_P + ppos] = f2h2(cc[nt][0], cc[nt][1]);
        Ps[r2 * PJ_P + ppos] = f2h2(cc[nt][2], cc[nt][3]);
    }
    __syncwarp();

    float o[4][4];
    #pragma unroll
    for (int nt = 0; nt < 4; ++nt)
        #pragma unroll
        for (int q = 0; q < 4; ++q) o[nt][q] = 0.f;
    #pragma unroll
    for (int kk = 0; kk < 4; ++kk) {
        const int k0 = kk * 8 + 2 * c;
        const uint2 P1 = *(const uint2*)(Ps + r1 * PJ_P + k0);
        const uint2 P2 = *(const uint2*)(Ps + r2 * PJ_P + k0);
        const uint32_t ap[4] = {P1.x, P2.x, P1.y, P2.y};
        #pragma unroll
        for (int nt = 0; nt < 4; ++nt) {
            const uint2 B = *(const uint2*)(VT + (nt * 8 + (lane >> 2)) * PJ_P + k0);
            mma16(o[nt], ap, B);
        }
    }

    const float inv1 = 1.f / sum1, inv2 = 1.f / sum2;
    #pragma unroll
    for (int nt = 0; nt < 4; ++nt) {
        const int idx = 8 * (nt >> 1) + 2 * c + (nt & 1);
        if (r1 < SEQ)
            g_attn[(((size_t)b * NWIN + win) * SEQ + r1) * 64 + head * 16 + idx] =
                f2h2(o[nt][0] * inv1, o[nt][1] * inv1);
        if (r2 < SEQ)
            g_attn[(((size_t)b * NWIN + win) * SEQ + r2) * 64 + head * 16 + idx] =
                f2h2(o[nt][2] * inv2, o[nt][3] * inv2);
    }
}

// ---------------------------------------------------------------------------
// Kernel 3: output projection via cp.async tiles + bias + inverse-roll scatter.
// ---------------------------------------------------------------------------
__global__ __launch_bounds__(256, 2) void proj_mma_kernel(const float* __restrict__ b_out,
                                                          float* __restrict__ out) {
    extern __shared__ uint32_t sh[];
    uint32_t* As = sh;
    uint32_t* Bs = sh + 64 * PKH;

    const int mtile = blockIdx.x, b = blockIdx.z;
    const int tid = threadIdx.x, lane = tid & 31, wid = tid >> 5;

    // A: cp.async from g_attn (already fp16 interleaved). 1024 uint4.
    #pragma unroll
    for (int it = 0; it < 4; ++it) {
        const int idx = tid + 256 * it;
        const int row = idx >> 4, c4 = idx & 15;
        cp_async16(smem_u32(As + row * PKH + c4 * 4),
                   g_attn + ((size_t)b * MPB + mtile * 64 + row) * 64 + c4 * 4);
    }
    // B: cp.async from preconverted w_out. 2048 uint4.
    #pragma unroll
    for (int it = 0; it < 8; ++it) {
        const int idx = tid + 256 * it;
        const int row = idx >> 4, c4 = idx & 15;
        cp_async16(smem_u32(Bs + row * PKH + c4 * 4),
                   g_wout_h + (size_t)row * 64 + c4 * 4);
    }
    cp_commit();
    cp_wait<0>();
    __syncthreads();

    const int wm = wid & 1, wn = wid >> 1;
    const int m0 = wm * 32, n0 = wn * 32;

    float acc[2][4][4];
    #pragma unroll
    for (int mt = 0; mt < 2; ++mt)
        #pragma unroll
        for (int nt = 0; nt < 4; ++nt)
            #pragma unroll
            for (int q = 0; q < 4; ++q) acc[mt][nt][q] = 0.f;

    #pragma unroll
    for (int kk = 0; kk < 8; ++kk) {
        const int k0 = kk * 8 + 2 * (lane & 3);
        const uint32_t* ar = As + (m0 + (lane >> 2)) * PKH + k0;
        const uint2 A10 = *(const uint2*)(ar);
        const uint2 A11 = *(const uint2*)(ar + 8 * PKH);
        const uint2 A20 = *(const uint2*)(ar + 16 * PKH);
        const uint2 A21 = *(const uint2*)(ar + 24 * PKH);
        const uint32_t a0[4] = {A10.x, A11.x, A10.y, A11.y};
        const uint32_t a1[4] = {A20.x, A21.x, A20.y, A21.y};
        #pragma unroll
        for (int nt = 0; nt < 4; ++nt) {
            const uint2 B = *(const uint2*)(Bs + (n0 + nt * 8 + (lane >> 2)) * PKH + k0);
            mma16(acc[0][nt], a0, B);
            mma16(acc[1][nt], a1, B);
        }
    }

    #pragma unroll
    for (int mt = 0; mt < 2; ++mt) {
        #pragma unroll
        for (int hh = 0; hh < 2; ++hh) {
            const int m = mtile * 64 + m0 + mt * 16 + hh * 8 + (lane >> 2);
            const int win = m / 49, s = m - win * 49;
            const int wr = win >> 3, wc = win & 7;
            const int i = s / 7, j = s - i * 7;
            int gh = wr * 7 + i + DISP; if (gh >= HW) gh -= HW;
            int gw = wc * 7 + j + DISP; if (gw >= HW) gw -= HW;
            float* orow = out + (((size_t)b * HW + gh) * HW + gw) * CH;
            #pragma unroll
            for (int nt = 0; nt < 4; ++nt) {
                const int n = n0 + nt * 8 + 2 * (lane & 3);
                float2 val = (hh == 0)
                    ? make_float2(acc[mt][nt][0], acc[mt][nt][1])
                    : make_float2(acc[mt][nt][2], acc[mt][nt][3]);
                val.x += __ldg(b_out + n);
                val.y += __ldg(b_out + n + 1);
                *(float2*)(orow + n) = val;
            }
        }
    }
}

extern "C" void kernel_launch(void* const* d_in, const int* in_sizes, int n_in,
                              void* d_out, int out_size) {
    const float* x      = (const float*)d_in[0];
    const float* w_qkv  = (const float*)d_in[1];
    const float* pos    = (const float*)d_in[2];
    const float* w_out  = (const float*)d_in[3];
    const float* b_out  = (const float*)d_in[4];
    float* out = (float*)d_out;

    cudaFuncSetAttribute(qkv_mma_kernel,  cudaFuncAttributeMaxDynamicSharedMemorySize, QKV_SMEM);
    cudaFuncSetAttribute(proj_mma_kernel, cudaFuncAttributeMaxDynamicSharedMemorySize, PROJ_SMEM);

    wconv_kernel<<<16, 256>>>(w_qkv, w_out);
    qkv_mma_kernel<<<dim3(MT64, 1, BATCH), 256, QKV_SMEM>>>(x);
    attn_mma_kernel<<<BATCH * NWIN * HEADS, 128>>>(pos);
    proj_mma_kernel<<<dim3(MT64, 1, BATCH), 256, PROJ_SMEM>>>(b_out, out);
}